// round 10
// baseline (speedup 1.0000x reference)
#include <cuda_runtime.h>
#include <cuda_bf16.h>
#include <stdint.h>

#define S_LEN 2048
#define DM 512
#define NH 8
#define WIN 64
#define SCALE 0.125f
#define WSZ (512*512)
#define XSZ (2048*512)

// ---------------- scratch (no allocation allowed) ----------------
__device__ __align__(16) __nv_bfloat16 g_x_hi[XSZ], g_x_lo[XSZ];
__device__ __align__(16) __nv_bfloat16 g_w_hi[4 * WSZ], g_w_lo[4 * WSZ];
__device__ __align__(16) __nv_bfloat16 g_q_hi[XSZ], g_q_lo[XSZ];
__device__ __align__(16) __nv_bfloat16 g_k_hi[XSZ], g_k_lo[XSZ];
__device__ __align__(16) __nv_bfloat16 g_vt_hi[XSZ], g_vt_lo[XSZ];   // [512][2048]
__device__ __align__(16) __nv_bfloat16 g_a_hi[XSZ], g_a_lo[XSZ];

// ---------------- PTX helpers (baseline sm_80+, compile for compute_103) -----
__device__ __forceinline__ uint32_t smem_u32(const void* p) {
    uint32_t a;
    asm("{ .reg .u64 t; cvta.to.shared.u64 t, %1; cvt.u32.u64 %0, t; }"
        : "=r"(a) : "l"(p));
    return a;
}
__device__ __forceinline__ void cp16(uint32_t s, const void* g) {
    asm volatile("cp.async.cg.shared.global [%0], [%1], 16;"
                 :: "r"(s), "l"(g) : "memory");
}
__device__ __forceinline__ void cp_commit() {
    asm volatile("cp.async.commit_group;" ::: "memory");
}
template<int N> __device__ __forceinline__ void cp_wait() {
    asm volatile("cp.async.wait_group %0;" :: "n"(N) : "memory");
}
__device__ __forceinline__ void ldsm_x4(uint32_t& r0, uint32_t& r1,
                                        uint32_t& r2, uint32_t& r3, uint32_t a) {
    asm volatile("ldmatrix.sync.aligned.m8n8.x4.shared.b16 {%0,%1,%2,%3}, [%4];"
                 : "=r"(r0), "=r"(r1), "=r"(r2), "=r"(r3) : "r"(a));
}
__device__ __forceinline__ void mma16816(float c[4], const uint32_t a[4],
                                         const uint32_t b[2]) {
    asm volatile(
        "mma.sync.aligned.m16n8k16.row.col.f32.bf16.bf16.f32 "
        "{%0,%1,%2,%3}, {%4,%5,%6,%7}, {%8,%9}, {%0,%1,%2,%3};"
        : "+f"(c[0]), "+f"(c[1]), "+f"(c[2]), "+f"(c[3])
        : "r"(a[0]), "r"(a[1]), "r"(a[2]), "r"(a[3]), "r"(b[0]), "r"(b[1]));
}

// ---------------- split conversion: fp32 -> (bf16 hi, bf16 lo) ----------------
__global__ __launch_bounds__(256)
void convert_split(const float* __restrict__ x,
                   const float* __restrict__ wq, const float* __restrict__ wk,
                   const float* __restrict__ wv, const float* __restrict__ wo)
{
    const int tn = blockIdx.y;
    const float* src = (tn == 0) ? x : (tn == 1) ? wq : (tn == 2) ? wk
                       : (tn == 3) ? wv : wo;
    const int n = (tn == 0) ? XSZ : WSZ;
    __nv_bfloat16* hi = (tn == 0) ? g_x_hi : g_w_hi + (tn - 1) * WSZ;
    __nv_bfloat16* lo = (tn == 0) ? g_x_lo : g_w_lo + (tn - 1) * WSZ;

    int i4 = (blockIdx.x * 256 + threadIdx.x) * 4;
    if (i4 >= n) return;
    float4 v = *reinterpret_cast<const float4*>(&src[i4]);
    __nv_bfloat16 h0 = __float2bfloat16(v.x);
    __nv_bfloat16 h1 = __float2bfloat16(v.y);
    __nv_bfloat16 h2 = __float2bfloat16(v.z);
    __nv_bfloat16 h3 = __float2bfloat16(v.w);
    __nv_bfloat16 l0 = __float2bfloat16(v.x - __bfloat162float(h0));
    __nv_bfloat16 l1 = __float2bfloat16(v.y - __bfloat162float(h1));
    __nv_bfloat16 l2 = __float2bfloat16(v.z - __bfloat162float(h2));
    __nv_bfloat16 l3 = __float2bfloat16(v.w - __bfloat162float(h3));
    reinterpret_cast<__nv_bfloat162*>(hi + i4)[0] = __halves2bfloat162(h0, h1);
    reinterpret_cast<__nv_bfloat162*>(hi + i4)[1] = __halves2bfloat162(h2, h3);
    reinterpret_cast<__nv_bfloat162*>(lo + i4)[0] = __halves2bfloat162(l0, l1);
    reinterpret_cast<__nv_bfloat162*>(lo + i4)[1] = __halves2bfloat162(l2, l3);
}

// ---------------- split-bf16 GEMM: 64x64 tile, 4-stage pipeline ---------------
// C = Ah·Bh^T + Ah·Bl^T + Al·Bh^T (+ bias). 16 chunks of K=32, 4-stage ring,
// prefetch distance 3, cp.async.wait_group<2> steady state.
// SMEM rows: 32 bf16 = 64B + 16B pad = 80B (banks r*20 mod 32: conflict-free).
#define OAL 5120
#define OBH 10240
#define OBL 15360
#define GBUF 20480
#define GEMM_SMEM (4 * GBUF)     // 81920 -> 2 CTAs/SM

__device__ __forceinline__ void gemm_body(
    const __nv_bfloat16* __restrict__ Ahi, const __nv_bfloat16* __restrict__ Alo,
    const __nv_bfloat16* __restrict__ Bhi, const __nv_bfloat16* __restrict__ Blo,
    const float* __restrict__ bias, int mode,
    __nv_bfloat16* __restrict__ oHi, __nv_bfloat16* __restrict__ oLo,
    float* __restrict__ oF, int rowBase, int colBase)
{
    extern __shared__ __align__(16) char dynsm[];
    const uint32_t sb = smem_u32(dynsm);
    const int tid = threadIdx.x, lane = tid & 31, wid = tid >> 5;
    const int wm = wid >> 2, wn = wid & 3;       // warps: 2 (m) x 4 (n), 32x16 tile
    const int a_row = (lane & 7) + ((lane >> 3) & 1) * 8, a_k = (lane >> 4) * 8;
    const int b_row = (lane & 7) + (lane >> 4) * 8,       b_k = ((lane >> 3) & 1) * 8;

    float acc[2][2][4] = {};

    auto stage = [&](int buf, int c) {
#pragma unroll
        for (int i = 0; i < 4; i++) {
            int idx = tid + i * 256;
            const __nv_bfloat16* src; int off, rbase;
            if (idx < 256)      { src = Ahi; off = 0;   rbase = rowBase; }
            else if (idx < 512) { src = Alo; off = OAL; rbase = rowBase; }
            else if (idx < 768) { src = Bhi; off = OBH; rbase = colBase; }
            else                { src = Blo; off = OBL; rbase = colBase; }
            int rem = idx & 255, row = rem >> 2, cc = rem & 3;
            cp16(sb + (uint32_t)(buf * GBUF + off + row * 80 + cc * 16),
                 src + ((size_t)(rbase + row) * DM + c * 32 + cc * 8));
        }
        cp_commit();
    };

    stage(0, 0); stage(1, 1); stage(2, 2);
    for (int c = 0; c < 16; c++) {
        if (c <= 13)      cp_wait<2>();
        else if (c == 14) cp_wait<1>();
        else              cp_wait<0>();
        __syncthreads();
        if (c < 13) stage((c + 3) & 3, c + 3);
        const uint32_t bb = sb + (uint32_t)((c & 3) * GBUF);
#pragma unroll
        for (int k16 = 0; k16 < 2; k16++) {
            uint32_t ah[2][4], al[2][4], bh[2][2], bl[2][2];
#pragma unroll
            for (int mi = 0; mi < 2; mi++) {
                uint32_t o = (uint32_t)((wm * 32 + mi * 16 + a_row) * 80 +
                                        (k16 * 16 + a_k) * 2);
                ldsm_x4(ah[mi][0], ah[mi][1], ah[mi][2], ah[mi][3], bb + o);
                ldsm_x4(al[mi][0], al[mi][1], al[mi][2], al[mi][3], bb + OAL + o);
            }
            {
                uint32_t o = (uint32_t)((wn * 16 + b_row) * 80 +
                                        (k16 * 16 + b_k) * 2);
                uint32_t r0, r1, r2, r3;
                ldsm_x4(r0, r1, r2, r3, bb + OBH + o);
                bh[0][0] = r0; bh[0][1] = r1; bh[1][0] = r2; bh[1][1] = r3;
                ldsm_x4(r0, r1, r2, r3, bb + OBL + o);
                bl[0][0] = r0; bl[0][1] = r1; bl[1][0] = r2; bl[1][1] = r3;
            }
#pragma unroll
            for (int mi = 0; mi < 2; mi++)
#pragma unroll
                for (int ni = 0; ni < 2; ni++) {
                    mma16816(acc[mi][ni], ah[mi], bh[ni]);
                    mma16816(acc[mi][ni], ah[mi], bl[ni]);
                    mma16816(acc[mi][ni], al[mi], bh[ni]);
                }
        }
    }

#pragma unroll
    for (int mi = 0; mi < 2; mi++) {
        int row = rowBase + wm * 32 + mi * 16 + (lane >> 2);
#pragma unroll
        for (int ni = 0; ni < 2; ni++) {
            int col = colBase + wn * 16 + ni * 8 + (lane & 3) * 2;
            float b0 = bias[col], b1 = bias[col + 1];
            float v00 = acc[mi][ni][0] + b0, v01 = acc[mi][ni][1] + b1;
            float v10 = acc[mi][ni][2] + b0, v11 = acc[mi][ni][3] + b1;
            if (mode == 2) {
                *reinterpret_cast<float2*>(&oF[(size_t)row * DM + col]) =
                    make_float2(v00, v01);
                *reinterpret_cast<float2*>(&oF[(size_t)(row + 8) * DM + col]) =
                    make_float2(v10, v11);
            } else if (mode == 0) {
                __nv_bfloat16 h00 = __float2bfloat16(v00), h01 = __float2bfloat16(v01);
                __nv_bfloat16 h10 = __float2bfloat16(v10), h11 = __float2bfloat16(v11);
                *reinterpret_cast<__nv_bfloat162*>(&oHi[(size_t)row * DM + col]) =
                    __halves2bfloat162(h00, h01);
                *reinterpret_cast<__nv_bfloat162*>(&oHi[(size_t)(row + 8) * DM + col]) =
                    __halves2bfloat162(h10, h11);
                *reinterpret_cast<__nv_bfloat162*>(&oLo[(size_t)row * DM + col]) =
                    __halves2bfloat162(__float2bfloat16(v00 - __bfloat162float(h00)),
                                       __float2bfloat16(v01 - __bfloat162float(h01)));
                *reinterpret_cast<__nv_bfloat162*>(&oLo[(size_t)(row + 8) * DM + col]) =
                    __halves2bfloat162(__float2bfloat16(v10 - __bfloat162float(h10)),
                                       __float2bfloat16(v11 - __bfloat162float(h11)));
            } else {
                __nv_bfloat16 hh;
                hh = __float2bfloat16(v00);
                oHi[(size_t)col * S_LEN + row] = hh;
                oLo[(size_t)col * S_LEN + row] = __float2bfloat16(v00 - __bfloat162float(hh));
                hh = __float2bfloat16(v01);
                oHi[(size_t)(col + 1) * S_LEN + row] = hh;
                oLo[(size_t)(col + 1) * S_LEN + row] = __float2bfloat16(v01 - __bfloat162float(hh));
                hh = __float2bfloat16(v10);
                oHi[(size_t)col * S_LEN + row + 8] = hh;
                oLo[(size_t)col * S_LEN + row + 8] = __float2bfloat16(v10 - __bfloat162float(hh));
                hh = __float2bfloat16(v11);
                oHi[(size_t)(col + 1) * S_LEN + row + 8] = hh;
                oLo[(size_t)(col + 1) * S_LEN + row + 8] = __float2bfloat16(v11 - __bfloat162float(hh));
            }
        }
    }
}

// QKV: grid (24, 32) = 768 CTAs.
__global__ __launch_bounds__(256, 2)
void gemm_qkv_mma(const float* __restrict__ bq, const float* __restrict__ bk,
                  const float* __restrict__ bv)
{
    const int which = blockIdx.x >> 3;
    const int colBase = (blockIdx.x & 7) * 64;
    const int rowBase = blockIdx.y * 64;
    const float* bias = (which == 0) ? bq : (which == 1) ? bk : bv;
    __nv_bfloat16 *oh, *ol; int mode;
    if (which == 0)      { oh = g_q_hi;  ol = g_q_lo;  mode = 0; }
    else if (which == 1) { oh = g_k_hi;  ol = g_k_lo;  mode = 0; }
    else                 { oh = g_vt_hi; ol = g_vt_lo; mode = 1; }
    gemm_body(g_x_hi, g_x_lo, g_w_hi + which * WSZ, g_w_lo + which * WSZ,
              bias, mode, oh, ol, nullptr, rowBase, colBase);
}

// O: grid (8, 32) = 256 CTAs.
__global__ __launch_bounds__(256, 2)
void gemm_o_mma(const float* __restrict__ bo, float* __restrict__ out)
{
    gemm_body(g_a_hi, g_a_lo, g_w_hi + 3 * WSZ, g_w_lo + 3 * WSZ,
              bo, 2, nullptr, nullptr, out, blockIdx.y * 64, blockIdx.x * 64);
}

// ---------------- tensor-core banded attention ------------------------------
#define AQH 0
#define AQL 9216
#define AKH 18432
#define AKL 46080
#define AVH 73728
#define AVL 99328
#define ASF 124928
#define APH AKH
#define APL AKL
#define ATTN_B 176128

__global__ __launch_bounds__(256)
void attn_mma()
{
    extern __shared__ __align__(16) char dynsm[];
    const uint32_t sb = smem_u32(dynsm);
    const int tid = threadIdx.x, lane = tid & 31, wid = tid >> 5;
    const int h = blockIdx.y;
    const int base = blockIdx.x * 64;
    const int j0 = base - WIN;

#pragma unroll
    for (int i = 0; i < 4; i++) {                       // Q
        int idx = tid + i * 256;
        int arr = idx >> 9, rem = idx & 511;
        int row = rem >> 3, cc = rem & 7;
        cp16(sb + (arr ? AQL : AQH) + (uint32_t)(row * 144 + cc * 16),
             (arr ? g_q_lo : g_q_hi) + ((size_t)(base + row) * DM + h * 64 + cc * 8));
    }
#pragma unroll
    for (int i = 0; i < 12; i++) {                      // K
        int idx = tid + i * 256;
        int arr = idx >= 1536 ? 1 : 0, rem = arr ? idx - 1536 : idx;
        int row = rem >> 3, cc = rem & 7;
        int j = j0 + row;
        uint32_t off = (arr ? AKL : AKH) + (uint32_t)(row * 144 + cc * 16);
        if (j >= 0 && j < S_LEN)
            cp16(sb + off, (arr ? g_k_lo : g_k_hi) + ((size_t)j * DM + h * 64 + cc * 8));
        else
            *reinterpret_cast<uint4*>(dynsm + off) = make_uint4(0, 0, 0, 0);
    }
#pragma unroll
    for (int i = 0; i < 12; i++) {                      // V^T
        int idx = tid + i * 256;
        int arr = idx >= 1536 ? 1 : 0, rem = arr ? idx - 1536 : idx;
        int row = rem / 24, cc = rem % 24;
        int j = j0 + cc * 8;
        uint32_t off = (arr ? AVL : AVH) + (uint32_t)(row * 400 + cc * 16);
        if (j >= 0 && j + 8 <= S_LEN)
            cp16(sb + off, (arr ? g_vt_lo : g_vt_hi) + ((size_t)(h * 64 + row) * S_LEN + j));
        else
            *reinterpret_cast<uint4*>(dynsm + off) = make_uint4(0, 0, 0, 0);
    }
    cp_commit();
    cp_wait<0>();
    __syncthreads();

    const int a_row = (lane & 7) + ((lane >> 3) & 1) * 8, a_k = (lane >> 4) * 8;
    const int b_row = (lane & 7) + (lane >> 4) * 8,       b_k = ((lane >> 3) & 1) * 8;
    const int wm = wid >> 1, wn = wid & 1;

    // ---- S = Q·K^T ----
    {
        float sacc[12][4] = {};
#pragma unroll
        for (int k16 = 0; k16 < 4; k16++) {
            uint32_t ah[4], al[4];
            uint32_t oA = (uint32_t)((wm * 16 + a_row) * 144 + (k16 * 16 + a_k) * 2);
            ldsm_x4(ah[0], ah[1], ah[2], ah[3], sb + AQH + oA);
            ldsm_x4(al[0], al[1], al[2], al[3], sb + AQL + oA);
#pragma unroll
            for (int t = 0; t < 6; t++) {
                uint32_t oB = (uint32_t)((wn * 96 + t * 16 + b_row) * 144 +
                                         (k16 * 16 + b_k) * 2);
                uint32_t r0, r1, r2, r3, b0[2], b1[2], c0[2], c1[2];
                ldsm_x4(r0, r1, r2, r3, sb + AKH + oB);
                b0[0] = r0; b0[1] = r1; b1[0] = r2; b1[1] = r3;
                ldsm_x4(r0, r1, r2, r3, sb + AKL + oB);
                c0[0] = r0; c0[1] = r1; c1[0] = r2; c1[1] = r3;
                mma16816(sacc[t * 2], ah, b0);
                mma16816(sacc[t * 2], ah, c0);
                mma16816(sacc[t * 2], al, b0);
                mma16816(sacc[t * 2 + 1], ah, b1);
                mma16816(sacc[t * 2 + 1], ah, c1);
                mma16816(sacc[t * 2 + 1], al, b1);
            }
        }
        float* S = reinterpret_cast<float*>(dynsm + ASF);
        int row = wm * 16 + (lane >> 2);
#pragma unroll
        for (int t = 0; t < 12; t++) {
            int col = wn * 96 + t * 8 + (lane & 3) * 2;
            *reinterpret_cast<float2*>(&S[row * 200 + col]) =
                make_float2(sacc[t][0], sacc[t][1]);
            *reinterpret_cast<float2*>(&S[(row + 8) * 200 + col]) =
                make_float2(sacc[t][2], sacc[t][3]);
        }
    }
    __syncthreads();

    // ---- masked softmax; write normalized P (bf16 hi/lo) over K ----
    {
        float* S = reinterpret_cast<float*>(dynsm + ASF);
#pragma unroll
        for (int r8 = 0; r8 < 8; r8++) {
            int m = wid * 8 + r8;
            int nlo = m, nhi = m + 128;
            if (-j0 > nlo) nlo = -j0;
            if (2047 - j0 < nhi) nhi = 2047 - j0;
            float v[6], mx = -1e30f;
#pragma unroll
            for (int i = 0; i < 6; i++) {
                int n = lane + 32 * i;
                float sv = S[m * 200 + n] * SCALE;
                v[i] = (n >= nlo && n <= nhi) ? sv : -1e30f;
                mx = fmaxf(mx, v[i]);
            }
#pragma unroll
            for (int o = 16; o; o >>= 1)
                mx = fmaxf(mx, __shfl_xor_sync(0xffffffffu, mx, o));
            float e[6], sum = 0.f;
#pragma unroll
            for (int i = 0; i < 6; i++) { e[i] = __expf(v[i] - mx); sum += e[i]; }
#pragma unroll
            for (int o = 16; o; o >>= 1)
                sum += __shfl_xor_sync(0xffffffffu, sum, o);
            float inv = 1.f / sum;
#pragma unroll
            for (int i = 0; i < 6; i++) {
                int n = lane + 32 * i;
                float p = e[i] * inv;
                __nv_bfloat16 ph = __float2bfloat16(p);
                __nv_bfloat16 pl = __float2bfloat16(p - __bfloat162float(ph));
                *reinterpret_cast<__nv_bfloat16*>(dynsm + APH + m * 400 + n * 2) = ph;
                *reinterpret_cast<__nv_bfloat16*>(dynsm + APL + m * 400 + n * 2) = pl;
            }
        }
    }
    __syncthreads();

    // ---- O = P·V ----
    {
        float oacc[4][4] = {};
#pragma unroll
        for (int k16 = 0; k16 < 12; k16++) {
            uint32_t ph[4], pl[4];
            uint32_t oA = (uint32_t)((wm * 16 + a_row) * 400 + (k16 * 16 + a_k) * 2);
            ldsm_x4(ph[0], ph[1], ph[2], ph[3], sb + APH + oA);
            ldsm_x4(pl[0], pl[1], pl[2], pl[3], sb + APL + oA);
#pragma unroll
            for (int bn = 0; bn < 2; bn++) {
                uint32_t oB = (uint32_t)((wn * 32 + bn * 16 + b_row) * 400 +
                                         (k16 * 16 + b_k) * 2);
                uint32_t r0, r1, r2, r3, vh0[2], vh1[2], vl0[2], vl1[2];
                ldsm_x4(r0, r1, r2, r3, sb + AVH + oB);
                vh0[0] = r0; vh0[1] = r1; vh1[0] = r2; vh1[1] = r3;
                ldsm_x4(r0, r1, r2, r3, sb + AVL + oB);
                vl0[0] = r0; vl0[1] = r1; vl1[0] = r2; vl1[1] = r3;
                mma16816(oacc[bn * 2], ph, vh0);
                mma16816(oacc[bn * 2], ph, vl0);
                mma16816(oacc[bn * 2], pl, vh0);
                mma16816(oacc[bn * 2 + 1], ph, vh1);
                mma16816(oacc[bn * 2 + 1], ph, vl1);
                mma16816(oacc[bn * 2 + 1], pl, vh1);
            }
        }
        int row = base + wm * 16 + (lane >> 2);
#pragma unroll
        for (int t = 0; t < 4; t++) {
            int col = h * 64 + wn * 32 + t * 8 + (lane & 3) * 2;
            float v00 = oacc[t][0], v01 = oacc[t][1];
            float v10 = oacc[t][2], v11 = oacc[t][3];
            __nv_bfloat16 h00 = __float2bfloat16(v00), h01 = __float2bfloat16(v01);
            __nv_bfloat16 h10 = __float2bfloat16(v10), h11 = __float2bfloat16(v11);
            *reinterpret_cast<__nv_bfloat162*>(&g_a_hi[(size_t)row * DM + col]) =
                __halves2bfloat162(h00, h01);
            *reinterpret_cast<__nv_bfloat162*>(&g_a_hi[(size_t)(row + 8) * DM + col]) =
                __halves2bfloat162(h10, h11);
            *reinterpret_cast<__nv_bfloat162*>(&g_a_lo[(size_t)row * DM + col]) =
                __halves2bfloat162(__float2bfloat16(v00 - __bfloat162float(h00)),
                                   __float2bfloat16(v01 - __bfloat162float(h01)));
            *reinterpret_cast<__nv_bfloat162*>(&g_a_lo[(size_t)(row + 8) * DM + col]) =
                __halves2bfloat162(__float2bfloat16(v10 - __bfloat162float(h10)),
                                   __float2bfloat16(v11 - __bfloat162float(h11)));
        }
    }
}

// ---------------- launch ----------------
extern "C" void kernel_launch(void* const* d_in, const int* in_sizes, int n_in,
                              void* d_out, int out_size) {
    const float* x  = (const float*)d_in[0];
    const float* Wq = (const float*)d_in[1];
    const float* bq = (const float*)d_in[2];
    const float* Wk = (const float*)d_in[3];
    const float* bk = (const float*)d_in[4];
    const float* Wv = (const float*)d_in[5];
    const float* bv = (const float*)d_in[6];
    const float* Wo = (const float*)d_in[7];
    const float* bo = (const float*)d_in[8];
    float* out = (float*)d_out;

    cudaFuncSetAttribute(gemm_qkv_mma, cudaFuncAttributeMaxDynamicSharedMemorySize, GEMM_SMEM);
    cudaFuncSetAttribute(gemm_o_mma, cudaFuncAttributeMaxDynamicSharedMemorySize, GEMM_SMEM);
    cudaFuncSetAttribute(attn_mma, cudaFuncAttributeMaxDynamicSharedMemorySize, ATTN_B);

    convert_split<<<dim3(XSZ / 1024, 5), 256>>>(x, Wq, Wk, Wv, Wo);

    gemm_qkv_mma<<<dim3(24, 32), 256, GEMM_SMEM>>>(bq, bk, bv);

    attn_mma<<<dim3(32, 8), 256, ATTN_B>>>();

    gemm_o_mma<<<dim3(8, 32), 256, GEMM_SMEM>>>(bo, out);
}

// round 11
// speedup vs baseline: 1.3545x; 1.3545x over previous
#include <cuda_runtime.h>
#include <cuda_fp16.h>
#include <stdint.h>

#define S_LEN 2048
#define DM 512
#define NH 8
#define WIN 64
#define SCALE 0.125f
#define WSZ (512*512)
#define XSZ (2048*512)

// ---------------- scratch (no allocation allowed) ----------------
__device__ __align__(16) __half g_x_hi[XSZ], g_x_lo[XSZ];
__device__ __align__(16) __half g_w_hi[4 * WSZ];                 // weights: hi only
__device__ __align__(16) __half g_q_hi[XSZ], g_q_lo[XSZ];
__device__ __align__(16) __half g_k_hi[XSZ], g_k_lo[XSZ];
__device__ __align__(16) __half g_vt_hi[XSZ], g_vt_lo[XSZ];      // [512][2048]
__device__ __align__(16) __half g_a_hi[XSZ], g_a_lo[XSZ];

// ---------------- PTX helpers (baseline sm_80+, compile for compute_103) -----
__device__ __forceinline__ uint32_t smem_u32(const void* p) {
    uint32_t a;
    asm("{ .reg .u64 t; cvta.to.shared.u64 t, %1; cvt.u32.u64 %0, t; }"
        : "=r"(a) : "l"(p));
    return a;
}
__device__ __forceinline__ void cp16(uint32_t s, const void* g) {
    asm volatile("cp.async.cg.shared.global [%0], [%1], 16;"
                 :: "r"(s), "l"(g) : "memory");
}
__device__ __forceinline__ void cp_commit() {
    asm volatile("cp.async.commit_group;" ::: "memory");
}
template<int N> __device__ __forceinline__ void cp_wait() {
    asm volatile("cp.async.wait_group %0;" :: "n"(N) : "memory");
}
__device__ __forceinline__ void ldsm_x4(uint32_t& r0, uint32_t& r1,
                                        uint32_t& r2, uint32_t& r3, uint32_t a) {
    asm volatile("ldmatrix.sync.aligned.m8n8.x4.shared.b16 {%0,%1,%2,%3}, [%4];"
                 : "=r"(r0), "=r"(r1), "=r"(r2), "=r"(r3) : "r"(a));
}
__device__ __forceinline__ void mma16816(float c[4], const uint32_t a[4],
                                         const uint32_t b[2]) {
    asm volatile(
        "mma.sync.aligned.m16n8k16.row.col.f32.f16.f16.f32 "
        "{%0,%1,%2,%3}, {%4,%5,%6,%7}, {%8,%9}, {%0,%1,%2,%3};"
        : "+f"(c[0]), "+f"(c[1]), "+f"(c[2]), "+f"(c[3])
        : "r"(a[0]), "r"(a[1]), "r"(a[2]), "r"(a[3]), "r"(b[0]), "r"(b[1]));
}

// ---------------- split conversion: fp32 -> fp16 (hi, and lo for x only) -----
__global__ __launch_bounds__(256)
void convert_split(const float* __restrict__ x,
                   const float* __restrict__ wq, const float* __restrict__ wk,
                   const float* __restrict__ wv, const float* __restrict__ wo)
{
    const int tn = blockIdx.y;
    const float* src = (tn == 0) ? x : (tn == 1) ? wq : (tn == 2) ? wk
                       : (tn == 3) ? wv : wo;
    const int n = (tn == 0) ? XSZ : WSZ;
    int i4 = (blockIdx.x * 256 + threadIdx.x) * 4;
    if (i4 >= n) return;
    float4 v = *reinterpret_cast<const float4*>(&src[i4]);
    __half h0 = __float2half_rn(v.x), h1 = __float2half_rn(v.y);
    __half h2 = __float2half_rn(v.z), h3 = __float2half_rn(v.w);
    if (tn == 0) {
        reinterpret_cast<__half2*>(g_x_hi + i4)[0] = __halves2half2(h0, h1);
        reinterpret_cast<__half2*>(g_x_hi + i4)[1] = __halves2half2(h2, h3);
        __half l0 = __float2half_rn(v.x - __half2float(h0));
        __half l1 = __float2half_rn(v.y - __half2float(h1));
        __half l2 = __float2half_rn(v.z - __half2float(h2));
        __half l3 = __float2half_rn(v.w - __half2float(h3));
        reinterpret_cast<__half2*>(g_x_lo + i4)[0] = __halves2half2(l0, l1);
        reinterpret_cast<__half2*>(g_x_lo + i4)[1] = __halves2half2(l2, l3);
    } else {
        __half* hi = g_w_hi + (tn - 1) * WSZ;
        reinterpret_cast<__half2*>(hi + i4)[0] = __halves2half2(h0, h1);
        reinterpret_cast<__half2*>(hi + i4)[1] = __halves2half2(h2, h3);
    }
}

// ---------------- 2-term fp16 GEMM: 64x64 tile, K-chunk=64, 144B rows --------
// C = (Ah + Al)·Bh^T (+ bias).  A = activations (exact 2-term split),
// B = weights (single fp16; the only rounding source, ~2.8e-4 RMS).
#define OAL 9216
#define OBH 18432
#define GBUF 27648
#define GEMM_SMEM (2 * GBUF)     // 55296

__device__ __forceinline__ void gemm_body(
    const __half* __restrict__ Ahi, const __half* __restrict__ Alo,
    const __half* __restrict__ Bhi,
    const float* __restrict__ bias, int mode,
    __half* __restrict__ oHi, __half* __restrict__ oLo,
    float* __restrict__ oF, int rowBase, int colBase)
{
    extern __shared__ __align__(16) char dynsm[];
    const uint32_t sb = smem_u32(dynsm);
    const int tid = threadIdx.x, lane = tid & 31, wid = tid >> 5;
    const int wm = wid >> 1, wn = wid & 1;       // warps: 2 (m) x 2 (n), 32x32
    const int a_row = (lane & 7) + ((lane >> 3) & 1) * 8, a_k = (lane >> 4) * 8;
    const int b_row = (lane & 7) + (lane >> 4) * 8,       b_k = ((lane >> 3) & 1) * 8;

    float acc[2][4][4] = {};

    auto stage = [&](int buf, int c) {
#pragma unroll
        for (int i = 0; i < 12; i++) {           // 1536 cp16 / 128 thr
            int idx = tid + i * 128;
            const __half* src; int off, rbase, rem;
            if (idx < 512)       { src = Ahi; off = 0;   rbase = rowBase; rem = idx; }
            else if (idx < 1024) { src = Alo; off = OAL; rbase = rowBase; rem = idx - 512; }
            else                 { src = Bhi; off = OBH; rbase = colBase; rem = idx - 1024; }
            int row = rem >> 3, cc = rem & 7;
            cp16(sb + (uint32_t)(buf * GBUF + off + row * 144 + cc * 16),
                 src + ((size_t)(rbase + row) * DM + c * 64 + cc * 8));
        }
        cp_commit();
    };

    stage(0, 0);
    for (int c = 0; c < 8; c++) {
        cp_wait<0>();
        __syncthreads();
        if (c < 7) stage((c + 1) & 1, c + 1);
        const uint32_t bb = sb + (uint32_t)((c & 1) * GBUF);
#pragma unroll
        for (int k16 = 0; k16 < 4; k16++) {
            uint32_t ah[2][4], al[2][4], bh[4][2];
#pragma unroll
            for (int mi = 0; mi < 2; mi++) {
                uint32_t o = (uint32_t)((wm * 32 + mi * 16 + a_row) * 144 +
                                        (k16 * 16 + a_k) * 2);
                ldsm_x4(ah[mi][0], ah[mi][1], ah[mi][2], ah[mi][3], bb + o);
                ldsm_x4(al[mi][0], al[mi][1], al[mi][2], al[mi][3], bb + OAL + o);
            }
#pragma unroll
            for (int bn = 0; bn < 2; bn++) {
                uint32_t o = (uint32_t)((wn * 32 + bn * 16 + b_row) * 144 +
                                        (k16 * 16 + b_k) * 2);
                uint32_t r0, r1, r2, r3;
                ldsm_x4(r0, r1, r2, r3, bb + OBH + o);
                bh[bn * 2][0] = r0; bh[bn * 2][1] = r1;
                bh[bn * 2 + 1][0] = r2; bh[bn * 2 + 1][1] = r3;
            }
#pragma unroll
            for (int mi = 0; mi < 2; mi++)
#pragma unroll
                for (int ni = 0; ni < 4; ni++) {
                    mma16816(acc[mi][ni], ah[mi], bh[ni]);
                    mma16816(acc[mi][ni], al[mi], bh[ni]);
                }
        }
    }

#pragma unroll
    for (int mi = 0; mi < 2; mi++) {
        int row = rowBase + wm * 32 + mi * 16 + (lane >> 2);
#pragma unroll
        for (int ni = 0; ni < 4; ni++) {
            int col = colBase + wn * 32 + ni * 8 + (lane & 3) * 2;
            float b0 = bias[col], b1 = bias[col + 1];
            float v00 = acc[mi][ni][0] + b0, v01 = acc[mi][ni][1] + b1;
            float v10 = acc[mi][ni][2] + b0, v11 = acc[mi][ni][3] + b1;
            if (mode == 2) {
                *reinterpret_cast<float2*>(&oF[(size_t)row * DM + col]) =
                    make_float2(v00, v01);
                *reinterpret_cast<float2*>(&oF[(size_t)(row + 8) * DM + col]) =
                    make_float2(v10, v11);
            } else if (mode == 0) {
                __half h00 = __float2half_rn(v00), h01 = __float2half_rn(v01);
                __half h10 = __float2half_rn(v10), h11 = __float2half_rn(v11);
                *reinterpret_cast<__half2*>(&oHi[(size_t)row * DM + col]) =
                    __halves2half2(h00, h01);
                *reinterpret_cast<__half2*>(&oHi[(size_t)(row + 8) * DM + col]) =
                    __halves2half2(h10, h11);
                *reinterpret_cast<__half2*>(&oLo[(size_t)row * DM + col]) =
                    __halves2half2(__float2half_rn(v00 - __half2float(h00)),
                                   __float2half_rn(v01 - __half2float(h01)));
                *reinterpret_cast<__half2*>(&oLo[(size_t)(row + 8) * DM + col]) =
                    __halves2half2(__float2half_rn(v10 - __half2float(h10)),
                                   __float2half_rn(v11 - __half2float(h11)));
            } else {
                __half hh;
                hh = __float2half_rn(v00);
                oHi[(size_t)col * S_LEN + row] = hh;
                oLo[(size_t)col * S_LEN + row] = __float2half_rn(v00 - __half2float(hh));
                hh = __float2half_rn(v01);
                oHi[(size_t)(col + 1) * S_LEN + row] = hh;
                oLo[(size_t)(col + 1) * S_LEN + row] = __float2half_rn(v01 - __half2float(hh));
                hh = __float2half_rn(v10);
                oHi[(size_t)col * S_LEN + row + 8] = hh;
                oLo[(size_t)col * S_LEN + row + 8] = __float2half_rn(v10 - __half2float(hh));
                hh = __float2half_rn(v11);
                oHi[(size_t)(col + 1) * S_LEN + row + 8] = hh;
                oLo[(size_t)(col + 1) * S_LEN + row + 8] = __float2half_rn(v11 - __half2float(hh));
            }
        }
    }
}

// QKV: grid (24, 32) = 768 CTAs.
__global__ __launch_bounds__(128, 3)
void gemm_qkv_mma(const float* __restrict__ bq, const float* __restrict__ bk,
                  const float* __restrict__ bv)
{
    const int which = blockIdx.x >> 3;
    const int colBase = (blockIdx.x & 7) * 64;
    const int rowBase = blockIdx.y * 64;
    const float* bias = (which == 0) ? bq : (which == 1) ? bk : bv;
    __half *oh, *ol; int mode;
    if (which == 0)      { oh = g_q_hi;  ol = g_q_lo;  mode = 0; }
    else if (which == 1) { oh = g_k_hi;  ol = g_k_lo;  mode = 0; }
    else                 { oh = g_vt_hi; ol = g_vt_lo; mode = 1; }
    gemm_body(g_x_hi, g_x_lo, g_w_hi + which * WSZ,
              bias, mode, oh, ol, nullptr, rowBase, colBase);
}

// O: grid (8, 32) = 256 CTAs.
__global__ __launch_bounds__(128, 3)
void gemm_o_mma(const float* __restrict__ bo, float* __restrict__ out)
{
    gemm_body(g_a_hi, g_a_lo, g_w_hi + 3 * WSZ,
              bo, 2, nullptr, nullptr, out, blockIdx.y * 64, blockIdx.x * 64);
}

// ---------------- tensor-core banded attention (fp16, 3-term: near-exact) ----
#define AQH 0
#define AQL 9216
#define AKH 18432
#define AKL 46080
#define AVH 73728
#define AVL 99328
#define ASF 124928
#define APH AKH
#define APL AKL
#define ATTN_B 176128

__global__ __launch_bounds__(256)
void attn_mma()
{
    extern __shared__ __align__(16) char dynsm[];
    const uint32_t sb = smem_u32(dynsm);
    const int tid = threadIdx.x, lane = tid & 31, wid = tid >> 5;
    const int h = blockIdx.y;
    const int base = blockIdx.x * 64;
    const int j0 = base - WIN;

#pragma unroll
    for (int i = 0; i < 4; i++) {                       // Q
        int idx = tid + i * 256;
        int arr = idx >> 9, rem = idx & 511;
        int row = rem >> 3, cc = rem & 7;
        cp16(sb + (arr ? AQL : AQH) + (uint32_t)(row * 144 + cc * 16),
             (arr ? g_q_lo : g_q_hi) + ((size_t)(base + row) * DM + h * 64 + cc * 8));
    }
#pragma unroll
    for (int i = 0; i < 12; i++) {                      // K
        int idx = tid + i * 256;
        int arr = idx >= 1536 ? 1 : 0, rem = arr ? idx - 1536 : idx;
        int row = rem >> 3, cc = rem & 7;
        int j = j0 + row;
        uint32_t off = (arr ? AKL : AKH) + (uint32_t)(row * 144 + cc * 16);
        if (j >= 0 && j < S_LEN)
            cp16(sb + off, (arr ? g_k_lo : g_k_hi) + ((size_t)j * DM + h * 64 + cc * 8));
        else
            *reinterpret_cast<uint4*>(dynsm + off) = make_uint4(0, 0, 0, 0);
    }
#pragma unroll
    for (int i = 0; i < 12; i++) {                      // V^T
        int idx = tid + i * 256;
        int arr = idx >= 1536 ? 1 : 0, rem = arr ? idx - 1536 : idx;
        int row = rem / 24, cc = rem % 24;
        int j = j0 + cc * 8;
        uint32_t off = (arr ? AVL : AVH) + (uint32_t)(row * 400 + cc * 16);
        if (j >= 0 && j + 8 <= S_LEN)
            cp16(sb + off, (arr ? g_vt_lo : g_vt_hi) + ((size_t)(h * 64 + row) * S_LEN + j));
        else
            *reinterpret_cast<uint4*>(dynsm + off) = make_uint4(0, 0, 0, 0);
    }
    cp_commit();
    cp_wait<0>();
    __syncthreads();

    const int a_row = (lane & 7) + ((lane >> 3) & 1) * 8, a_k = (lane >> 4) * 8;
    const int b_row = (lane & 7) + (lane >> 4) * 8,       b_k = ((lane >> 3) & 1) * 8;
    const int wm = wid >> 1, wn = wid & 1;

    // ---- S = Q·K^T ----
    {
        float sacc[12][4] = {};
#pragma unroll
        for (int k16 = 0; k16 < 4; k16++) {
            uint32_t ah[4], al[4];
            uint32_t oA = (uint32_t)((wm * 16 + a_row) * 144 + (k16 * 16 + a_k) * 2);
            ldsm_x4(ah[0], ah[1], ah[2], ah[3], sb + AQH + oA);
            ldsm_x4(al[0], al[1], al[2], al[3], sb + AQL + oA);
#pragma unroll
            for (int t = 0; t < 6; t++) {
                uint32_t oB = (uint32_t)((wn * 96 + t * 16 + b_row) * 144 +
                                         (k16 * 16 + b_k) * 2);
                uint32_t r0, r1, r2, r3, b0[2], b1[2], c0[2], c1[2];
                ldsm_x4(r0, r1, r2, r3, sb + AKH + oB);
                b0[0] = r0; b0[1] = r1; b1[0] = r2; b1[1] = r3;
                ldsm_x4(r0, r1, r2, r3, sb + AKL + oB);
                c0[0] = r0; c0[1] = r1; c1[0] = r2; c1[1] = r3;
                mma16816(sacc[t * 2], ah, b0);
                mma16816(sacc[t * 2], ah, c0);
                mma16816(sacc[t * 2], al, b0);
                mma16816(sacc[t * 2 + 1], ah, b1);
                mma16816(sacc[t * 2 + 1], ah, c1);
                mma16816(sacc[t * 2 + 1], al, b1);
            }
        }
        float* S = reinterpret_cast<float*>(dynsm + ASF);
        int row = wm * 16 + (lane >> 2);
#pragma unroll
        for (int t = 0; t < 12; t++) {
            int col = wn * 96 + t * 8 + (lane & 3) * 2;
            *reinterpret_cast<float2*>(&S[row * 200 + col]) =
                make_float2(sacc[t][0], sacc[t][1]);
            *reinterpret_cast<float2*>(&S[(row + 8) * 200 + col]) =
                make_float2(sacc[t][2], sacc[t][3]);
        }
    }
    __syncthreads();

    // ---- masked softmax; write normalized P (fp16 hi/lo) over K ----
    {
        float* S = reinterpret_cast<float*>(dynsm + ASF);
#pragma unroll
        for (int r8 = 0; r8 < 8; r8++) {
            int m = wid * 8 + r8;
            int nlo = m, nhi = m + 128;
            if (-j0 > nlo) nlo = -j0;
            if (2047 - j0 < nhi) nhi = 2047 - j0;
            float v[6], mx = -1e30f;
#pragma unroll
            for (int i = 0; i < 6; i++) {
                int n = lane + 32 * i;
                float sv = S[m * 200 + n] * SCALE;
                v[i] = (n >= nlo && n <= nhi) ? sv : -1e30f;
                mx = fmaxf(mx, v[i]);
            }
#pragma unroll
            for (int o = 16; o; o >>= 1)
                mx = fmaxf(mx, __shfl_xor_sync(0xffffffffu, mx, o));
            float e[6], sum = 0.f;
#pragma unroll
            for (int i = 0; i < 6; i++) { e[i] = __expf(v[i] - mx); sum += e[i]; }
#pragma unroll
            for (int o = 16; o; o >>= 1)
                sum += __shfl_xor_sync(0xffffffffu, sum, o);
            float inv = 1.f / sum;
#pragma unroll
            for (int i = 0; i < 6; i++) {
                int n = lane + 32 * i;
                float p = e[i] * inv;
                __half ph = __float2half_rn(p);
                __half pl = __float2half_rn(p - __half2float(ph));
                *reinterpret_cast<__half*>(dynsm + APH + m * 400 + n * 2) = ph;
                *reinterpret_cast<__half*>(dynsm + APL + m * 400 + n * 2) = pl;
            }
        }
    }
    __syncthreads();

    // ---- O = P·V ----
    {
        float oacc[4][4] = {};
#pragma unroll
        for (int k16 = 0; k16 < 12; k16++) {
            uint32_t ph[4], pl[4];
            uint32_t oA = (uint32_t)((wm * 16 + a_row) * 400 + (k16 * 16 + a_k) * 2);
            ldsm_x4(ph[0], ph[1], ph[2], ph[3], sb + APH + oA);
            ldsm_x4(pl[0], pl[1], pl[2], pl[3], sb + APL + oA);
#pragma unroll
            for (int bn = 0; bn < 2; bn++) {
                uint32_t oB = (uint32_t)((wn * 32 + bn * 16 + b_row) * 400 +
                                         (k16 * 16 + b_k) * 2);
                uint32_t r0, r1, r2, r3, vh0[2], vh1[2], vl0[2], vl1[2];
                ldsm_x4(r0, r1, r2, r3, sb + AVH + oB);
                vh0[0] = r0; vh0[1] = r1; vh1[0] = r2; vh1[1] = r3;
                ldsm_x4(r0, r1, r2, r3, sb + AVL + oB);
                vl0[0] = r0; vl0[1] = r1; vl1[0] = r2; vl1[1] = r3;
                mma16816(oacc[bn * 2], ph, vh0);
                mma16816(oacc[bn * 2], ph, vl0);
                mma16816(oacc[bn * 2], pl, vh0);
                mma16816(oacc[bn * 2 + 1], ph, vh1);
                mma16816(oacc[bn * 2 + 1], ph, vl1);
                mma16816(oacc[bn * 2 + 1], pl, vh1);
            }
        }
        int row = base + wm * 16 + (lane >> 2);
#pragma unroll
        for (int t = 0; t < 4; t++) {
            int col = h * 64 + wn * 32 + t * 8 + (lane & 3) * 2;
            float v00 = oacc[t][0], v01 = oacc[t][1];
            float v10 = oacc[t][2], v11 = oacc[t][3];
            __half h00 = __float2half_rn(v00), h01 = __float2half_rn(v01);
            __half h10 = __float2half_rn(v10), h11 = __float2half_rn(v11);
            *reinterpret_cast<__half2*>(&g_a_hi[(size_t)row * DM + col]) =
                __halves2half2(h00, h01);
            *reinterpret_cast<__half2*>(&g_a_hi[(size_t)(row + 8) * DM + col]) =
                __halves2half2(h10, h11);
            *reinterpret_cast<__half2*>(&g_a_lo[(size_t)row * DM + col]) =
                __halves2half2(__float2half_rn(v00 - __half2float(h00)),
                               __float2half_rn(v01 - __half2float(h01)));
            *reinterpret_cast<__half2*>(&g_a_lo[(size_t)(row + 8) * DM + col]) =
                __halves2half2(__float2half_rn(v10 - __half2float(h10)),
                               __float2half_rn(v11 - __half2float(h11)));
        }
    }
}

// ---------------- launch ----------------
extern "C" void kernel_launch(void* const* d_in, const int* in_sizes, int n_in,
                              void* d_out, int out_size) {
    const float* x  = (const float*)d_in[0];
    const float* Wq = (const float*)d_in[1];
    const float* bq = (const float*)d_in[2];
    const float* Wk = (const float*)d_in[3];
    const float* bk = (const float*)d_in[4];
    const float* Wv = (const float*)d_in[5];
    const float* bv = (const float*)d_in[6];
    const float* Wo = (const float*)d_in[7];
    const float* bo = (const float*)d_in[8];
    float* out = (float*)d_out;

    cudaFuncSetAttribute(gemm_qkv_mma, cudaFuncAttributeMaxDynamicSharedMemorySize, GEMM_SMEM);
    cudaFuncSetAttribute(gemm_o_mma, cudaFuncAttributeMaxDynamicSharedMemorySize, GEMM_SMEM);
    cudaFuncSetAttribute(attn_mma, cudaFuncAttributeMaxDynamicSharedMemorySize, ATTN_B);

    convert_split<<<dim3(XSZ / 1024, 5), 256>>>(x, Wq, Wk, Wv, Wo);

    gemm_qkv_mma<<<dim3(24, 32), 128, GEMM_SMEM>>>(bq, bk, bv);

    attn_mma<<<dim3(32, 8), 256, ATTN_B>>>();

    gemm_o_mma<<<dim3(8, 32), 128, GEMM_SMEM>>>(bo, out);
}

// round 12
// speedup vs baseline: 1.4887x; 1.0991x over previous
#include <cuda_runtime.h>
#include <cuda_fp16.h>
#include <stdint.h>

#define S_LEN 2048
#define DM 512
#define NH 8
#define WIN 64
#define SCALE 0.125f
#define WSZ (512*512)
#define XSZ (2048*512)

// ---------------- scratch (no allocation allowed) ----------------
__device__ __align__(16) __half g_x_hi[XSZ], g_x_lo[XSZ];
__device__ __align__(16) __half g_w_hi[4 * WSZ];                 // weights: hi only
__device__ __align__(16) __half g_q_hi[XSZ], g_q_lo[XSZ];
__device__ __align__(16) __half g_k_hi[XSZ];                     // K: hi only
__device__ __align__(16) __half g_vt_hi[XSZ];                    // V^T: hi only [512][2048]
__device__ __align__(16) __half g_a_hi[XSZ], g_a_lo[XSZ];

// ---------------- PTX helpers (baseline sm_80+, compile for compute_103) -----
__device__ __forceinline__ uint32_t smem_u32(const void* p) {
    uint32_t a;
    asm("{ .reg .u64 t; cvta.to.shared.u64 t, %1; cvt.u32.u64 %0, t; }"
        : "=r"(a) : "l"(p));
    return a;
}
__device__ __forceinline__ void cp16(uint32_t s, const void* g) {
    asm volatile("cp.async.cg.shared.global [%0], [%1], 16;"
                 :: "r"(s), "l"(g) : "memory");
}
__device__ __forceinline__ void cp_commit() {
    asm volatile("cp.async.commit_group;" ::: "memory");
}
template<int N> __device__ __forceinline__ void cp_wait() {
    asm volatile("cp.async.wait_group %0;" :: "n"(N) : "memory");
}
__device__ __forceinline__ void ldsm_x4(uint32_t& r0, uint32_t& r1,
                                        uint32_t& r2, uint32_t& r3, uint32_t a) {
    asm volatile("ldmatrix.sync.aligned.m8n8.x4.shared.b16 {%0,%1,%2,%3}, [%4];"
                 : "=r"(r0), "=r"(r1), "=r"(r2), "=r"(r3) : "r"(a));
}
__device__ __forceinline__ void mma16816(float c[4], const uint32_t a[4],
                                         const uint32_t b[2]) {
    asm volatile(
        "mma.sync.aligned.m16n8k16.row.col.f32.f16.f16.f32 "
        "{%0,%1,%2,%3}, {%4,%5,%6,%7}, {%8,%9}, {%0,%1,%2,%3};"
        : "+f"(c[0]), "+f"(c[1]), "+f"(c[2]), "+f"(c[3])
        : "r"(a[0]), "r"(a[1]), "r"(a[2]), "r"(a[3]), "r"(b[0]), "r"(b[1]));
}

// ---------------- split conversion: fp32 -> fp16 (hi, and lo for x only) -----
__global__ __launch_bounds__(256)
void convert_split(const float* __restrict__ x,
                   const float* __restrict__ wq, const float* __restrict__ wk,
                   const float* __restrict__ wv, const float* __restrict__ wo)
{
    const int tn = blockIdx.y;
    const float* src = (tn == 0) ? x : (tn == 1) ? wq : (tn == 2) ? wk
                       : (tn == 3) ? wv : wo;
    const int n = (tn == 0) ? XSZ : WSZ;
    int i4 = (blockIdx.x * 256 + threadIdx.x) * 4;
    if (i4 >= n) return;
    float4 v = *reinterpret_cast<const float4*>(&src[i4]);
    __half h0 = __float2half_rn(v.x), h1 = __float2half_rn(v.y);
    __half h2 = __float2half_rn(v.z), h3 = __float2half_rn(v.w);
    if (tn == 0) {
        reinterpret_cast<__half2*>(g_x_hi + i4)[0] = __halves2half2(h0, h1);
        reinterpret_cast<__half2*>(g_x_hi + i4)[1] = __halves2half2(h2, h3);
        __half l0 = __float2half_rn(v.x - __half2float(h0));
        __half l1 = __float2half_rn(v.y - __half2float(h1));
        __half l2 = __float2half_rn(v.z - __half2float(h2));
        __half l3 = __float2half_rn(v.w - __half2float(h3));
        reinterpret_cast<__half2*>(g_x_lo + i4)[0] = __halves2half2(l0, l1);
        reinterpret_cast<__half2*>(g_x_lo + i4)[1] = __halves2half2(l2, l3);
    } else {
        __half* hi = g_w_hi + (tn - 1) * WSZ;
        reinterpret_cast<__half2*>(hi + i4)[0] = __halves2half2(h0, h1);
        reinterpret_cast<__half2*>(hi + i4)[1] = __halves2half2(h2, h3);
    }
}

// ---------------- 2-term fp16 GEMM: BMx64 tile, K-chunk=64, 144B rows --------
// C = (Ah + Al)·Bh^T (+ bias). BM = 64 (qkv) or 32 (O, for a 512-CTA grid).
template<int BM>
__device__ __forceinline__ void gemm_body(
    const __half* __restrict__ Ahi, const __half* __restrict__ Alo,
    const __half* __restrict__ Bhi,
    const float* __restrict__ bias, int mode,
    __half* __restrict__ oHi, __half* __restrict__ oLo,
    float* __restrict__ oF, int rowBase, int colBase)
{
    constexpr int MI   = BM / 32;                  // m16 frags per warp
    constexpr int OAL  = BM * 144;
    constexpr int OBH  = 2 * BM * 144;
    constexpr int GBUF = (2 * BM + 64) * 144;
    constexpr int NAOP = BM * 8;                   // cp16 per A array
    constexpr int ITER = (2 * NAOP + 512) / 128;

    extern __shared__ __align__(16) char dynsm[];
    const uint32_t sb = smem_u32(dynsm);
    const int tid = threadIdx.x, lane = tid & 31, wid = tid >> 5;
    const int wm = wid >> 1, wn = wid & 1;         // warps: 2 (m) x 2 (n)
    const int a_row = (lane & 7) + ((lane >> 3) & 1) * 8, a_k = (lane >> 4) * 8;
    const int b_row = (lane & 7) + (lane >> 4) * 8,       b_k = ((lane >> 3) & 1) * 8;

    float acc[MI][4][4] = {};

    auto stage = [&](int buf, int c) {
#pragma unroll
        for (int i = 0; i < ITER; i++) {
            int idx = tid + i * 128;
            const __half* src; int off, rbase, rem;
            if (idx < NAOP)          { src = Ahi; off = 0;   rbase = rowBase; rem = idx; }
            else if (idx < 2 * NAOP) { src = Alo; off = OAL; rbase = rowBase; rem = idx - NAOP; }
            else                     { src = Bhi; off = OBH; rbase = colBase; rem = idx - 2 * NAOP; }
            int row = rem >> 3, cc = rem & 7;
            cp16(sb + (uint32_t)(buf * GBUF + off + row * 144 + cc * 16),
                 src + ((size_t)(rbase + row) * DM + c * 64 + cc * 8));
        }
        cp_commit();
    };

    stage(0, 0);
    for (int c = 0; c < 8; c++) {
        cp_wait<0>();
        __syncthreads();
        if (c < 7) stage((c + 1) & 1, c + 1);
        const uint32_t bb = sb + (uint32_t)((c & 1) * GBUF);
#pragma unroll
        for (int k16 = 0; k16 < 4; k16++) {
            uint32_t ah[MI][4], al[MI][4], bh[4][2];
#pragma unroll
            for (int mi = 0; mi < MI; mi++) {
                uint32_t o = (uint32_t)((wm * (BM / 2) + mi * 16 + a_row) * 144 +
                                        (k16 * 16 + a_k) * 2);
                ldsm_x4(ah[mi][0], ah[mi][1], ah[mi][2], ah[mi][3], bb + o);
                ldsm_x4(al[mi][0], al[mi][1], al[mi][2], al[mi][3], bb + OAL + o);
            }
#pragma unroll
            for (int bn = 0; bn < 2; bn++) {
                uint32_t o = (uint32_t)((wn * 32 + bn * 16 + b_row) * 144 +
                                        (k16 * 16 + b_k) * 2);
                uint32_t r0, r1, r2, r3;
                ldsm_x4(r0, r1, r2, r3, bb + OBH + o);
                bh[bn * 2][0] = r0; bh[bn * 2][1] = r1;
                bh[bn * 2 + 1][0] = r2; bh[bn * 2 + 1][1] = r3;
            }
#pragma unroll
            for (int mi = 0; mi < MI; mi++)
#pragma unroll
                for (int ni = 0; ni < 4; ni++) {
                    mma16816(acc[mi][ni], ah[mi], bh[ni]);
                    mma16816(acc[mi][ni], al[mi], bh[ni]);
                }
        }
    }

#pragma unroll
    for (int mi = 0; mi < MI; mi++) {
        int row = rowBase + wm * (BM / 2) + mi * 16 + (lane >> 2);
#pragma unroll
        for (int ni = 0; ni < 4; ni++) {
            int col = colBase + wn * 32 + ni * 8 + (lane & 3) * 2;
            float b0 = bias[col], b1 = bias[col + 1];
            float v00 = acc[mi][ni][0] + b0, v01 = acc[mi][ni][1] + b1;
            float v10 = acc[mi][ni][2] + b0, v11 = acc[mi][ni][3] + b1;
            if (mode == 2) {
                *reinterpret_cast<float2*>(&oF[(size_t)row * DM + col]) =
                    make_float2(v00, v01);
                *reinterpret_cast<float2*>(&oF[(size_t)(row + 8) * DM + col]) =
                    make_float2(v10, v11);
            } else if (mode == 0) {
                __half h00 = __float2half_rn(v00), h01 = __float2half_rn(v01);
                __half h10 = __float2half_rn(v10), h11 = __float2half_rn(v11);
                *reinterpret_cast<__half2*>(&oHi[(size_t)row * DM + col]) =
                    __halves2half2(h00, h01);
                *reinterpret_cast<__half2*>(&oHi[(size_t)(row + 8) * DM + col]) =
                    __halves2half2(h10, h11);
                if (oLo) {
                    *reinterpret_cast<__half2*>(&oLo[(size_t)row * DM + col]) =
                        __halves2half2(__float2half_rn(v00 - __half2float(h00)),
                                       __float2half_rn(v01 - __half2float(h01)));
                    *reinterpret_cast<__half2*>(&oLo[(size_t)(row + 8) * DM + col]) =
                        __halves2half2(__float2half_rn(v10 - __half2float(h10)),
                                       __float2half_rn(v11 - __half2float(h11)));
                }
            } else {
                oHi[(size_t)col * S_LEN + row] = __float2half_rn(v00);
                oHi[(size_t)(col + 1) * S_LEN + row] = __float2half_rn(v01);
                oHi[(size_t)col * S_LEN + row + 8] = __float2half_rn(v10);
                oHi[(size_t)(col + 1) * S_LEN + row + 8] = __float2half_rn(v11);
            }
        }
    }
}

#define QKV_SMEM ((2 * 64 + 64) * 144 * 2)   // 55296
#define O_SMEM   ((2 * 32 + 64) * 144 * 2)   // 36864

// QKV: grid (24, 32) = 768 CTAs.
__global__ __launch_bounds__(128, 3)
void gemm_qkv_mma(const float* __restrict__ bq, const float* __restrict__ bk,
                  const float* __restrict__ bv)
{
    const int which = blockIdx.x >> 3;
    const int colBase = (blockIdx.x & 7) * 64;
    const int rowBase = blockIdx.y * 64;
    const float* bias = (which == 0) ? bq : (which == 1) ? bk : bv;
    __half *oh, *ol; int mode;
    if (which == 0)      { oh = g_q_hi;  ol = g_q_lo; mode = 0; }
    else if (which == 1) { oh = g_k_hi;  ol = nullptr; mode = 0; }
    else                 { oh = g_vt_hi; ol = nullptr; mode = 1; }
    gemm_body<64>(g_x_hi, g_x_lo, g_w_hi + which * WSZ,
                  bias, mode, oh, ol, nullptr, rowBase, colBase);
}

// O: grid (8, 64) = 512 CTAs, 32-row tiles.
__global__ __launch_bounds__(128, 4)
void gemm_o_mma(const float* __restrict__ bo, float* __restrict__ out)
{
    gemm_body<32>(g_a_hi, g_a_lo, g_w_hi + 3 * WSZ,
                  bo, 2, nullptr, nullptr, out, blockIdx.y * 32, blockIdx.x * 64);
}

// ---------------- tensor-core banded attention (2-term) ----------------------
// S = (Qh+Ql)·Kh^T ; softmax ; O = (Ph+Pl)·Vh
#define AQH 0
#define AQL 9216
#define AKH 18432
#define AVH 46080
#define ASF 71680
#define APH AKH              /* P-hi overlays K after S is computed (25600<=27648) */
#define APL 122880
#define ATTN_B 148480

__global__ __launch_bounds__(256)
void attn_mma()
{
    extern __shared__ __align__(16) char dynsm[];
    const uint32_t sb = smem_u32(dynsm);
    const int tid = threadIdx.x, lane = tid & 31, wid = tid >> 5;
    const int h = blockIdx.y;
    const int base = blockIdx.x * 64;
    const int j0 = base - WIN;

#pragma unroll
    for (int i = 0; i < 4; i++) {                       // Q hi+lo [64][64]
        int idx = tid + i * 256;
        int arr = idx >> 9, rem = idx & 511;
        int row = rem >> 3, cc = rem & 7;
        cp16(sb + (arr ? AQL : AQH) + (uint32_t)(row * 144 + cc * 16),
             (arr ? g_q_lo : g_q_hi) + ((size_t)(base + row) * DM + h * 64 + cc * 8));
    }
#pragma unroll
    for (int i = 0; i < 6; i++) {                       // K hi [192][64]
        int idx = tid + i * 256;
        int row = idx >> 3, cc = idx & 7;
        int j = j0 + row;
        uint32_t off = AKH + (uint32_t)(row * 144 + cc * 16);
        if (j >= 0 && j < S_LEN)
            cp16(sb + off, g_k_hi + ((size_t)j * DM + h * 64 + cc * 8));
        else
            *reinterpret_cast<uint4*>(dynsm + off) = make_uint4(0, 0, 0, 0);
    }
#pragma unroll
    for (int i = 0; i < 6; i++) {                       // V^T hi [64][192]
        int idx = tid + i * 256;
        int row = idx / 24, cc = idx % 24;
        int j = j0 + cc * 8;
        uint32_t off = AVH + (uint32_t)(row * 400 + cc * 16);
        if (j >= 0 && j + 8 <= S_LEN)
            cp16(sb + off, g_vt_hi + ((size_t)(h * 64 + row) * S_LEN + j));
        else
            *reinterpret_cast<uint4*>(dynsm + off) = make_uint4(0, 0, 0, 0);
    }
    cp_commit();
    cp_wait<0>();
    __syncthreads();

    const int a_row = (lane & 7) + ((lane >> 3) & 1) * 8, a_k = (lane >> 4) * 8;
    const int b_row = (lane & 7) + (lane >> 4) * 8,       b_k = ((lane >> 3) & 1) * 8;
    const int wm = wid >> 1, wn = wid & 1;

    // ---- S = (Qh+Ql)·Kh^T ----
    {
        float sacc[12][4] = {};
#pragma unroll
        for (int k16 = 0; k16 < 4; k16++) {
            uint32_t ah[4], al[4];
            uint32_t oA = (uint32_t)((wm * 16 + a_row) * 144 + (k16 * 16 + a_k) * 2);
            ldsm_x4(ah[0], ah[1], ah[2], ah[3], sb + AQH + oA);
            ldsm_x4(al[0], al[1], al[2], al[3], sb + AQL + oA);
#pragma unroll
            for (int t = 0; t < 6; t++) {
                uint32_t oB = (uint32_t)((wn * 96 + t * 16 + b_row) * 144 +
                                         (k16 * 16 + b_k) * 2);
                uint32_t r0, r1, r2, r3, b0[2], b1[2];
                ldsm_x4(r0, r1, r2, r3, sb + AKH + oB);
                b0[0] = r0; b0[1] = r1; b1[0] = r2; b1[1] = r3;
                mma16816(sacc[t * 2], ah, b0);
                mma16816(sacc[t * 2], al, b0);
                mma16816(sacc[t * 2 + 1], ah, b1);
                mma16816(sacc[t * 2 + 1], al, b1);
            }
        }
        float* S = reinterpret_cast<float*>(dynsm + ASF);
        int row = wm * 16 + (lane >> 2);
#pragma unroll
        for (int t = 0; t < 12; t++) {
            int col = wn * 96 + t * 8 + (lane & 3) * 2;
            *reinterpret_cast<float2*>(&S[row * 200 + col]) =
                make_float2(sacc[t][0], sacc[t][1]);
            *reinterpret_cast<float2*>(&S[(row + 8) * 200 + col]) =
                make_float2(sacc[t][2], sacc[t][3]);
        }
    }
    __syncthreads();

    // ---- masked softmax; write normalized P (fp16 hi/lo) ----
    {
        float* S = reinterpret_cast<float*>(dynsm + ASF);
#pragma unroll
        for (int r8 = 0; r8 < 8; r8++) {
            int m = wid * 8 + r8;
            int nlo = m, nhi = m + 128;
            if (-j0 > nlo) nlo = -j0;
            if (2047 - j0 < nhi) nhi = 2047 - j0;
            float v[6], mx = -1e30f;
#pragma unroll
            for (int i = 0; i < 6; i++) {
                int n = lane + 32 * i;
                float sv = S[m * 200 + n] * SCALE;
                v[i] = (n >= nlo && n <= nhi) ? sv : -1e30f;
                mx = fmaxf(mx, v[i]);
            }
#pragma unroll
            for (int o = 16; o; o >>= 1)
                mx = fmaxf(mx, __shfl_xor_sync(0xffffffffu, mx, o));
            float e[6], sum = 0.f;
#pragma unroll
            for (int i = 0; i < 6; i++) { e[i] = __expf(v[i] - mx); sum += e[i]; }
#pragma unroll
            for (int o = 16; o; o >>= 1)
                sum += __shfl_xor_sync(0xffffffffu, sum, o);
            float inv = 1.f / sum;
#pragma unroll
            for (int i = 0; i < 6; i++) {
                int n = lane + 32 * i;
                float p = e[i] * inv;
                __half ph = __float2half_rn(p);
                __half pl = __float2half_rn(p - __half2float(ph));
                *reinterpret_cast<__half*>(dynsm + APH + m * 400 + n * 2) = ph;
                *reinterpret_cast<__half*>(dynsm + APL + m * 400 + n * 2) = pl;
            }
        }
    }
    __syncthreads();

    // ---- O = (Ph+Pl)·Vh ----
    {
        float oacc[4][4] = {};
#pragma unroll
        for (int k16 = 0; k16 < 12; k16++) {
            uint32_t ph[4], pl[4];
            uint32_t oA = (uint32_t)((wm * 16 + a_row) * 400 + (k16 * 16 + a_k) * 2);
            ldsm_x4(ph[0], ph[1], ph[2], ph[3], sb + APH + oA);
            ldsm_x4(pl[0], pl[1], pl[2], pl[3], sb + APL + oA);
#pragma unroll
            for (int bn = 0; bn < 2; bn++) {
                uint32_t oB = (uint32_t)((wn * 32 + bn * 16 + b_row) * 400 +
                                         (k16 * 16 + b_k) * 2);
                uint32_t r0, r1, r2, r3, vh0[2], vh1[2];
                ldsm_x4(r0, r1, r2, r3, sb + AVH + oB);
                vh0[0] = r0; vh0[1] = r1; vh1[0] = r2; vh1[1] = r3;
                mma16816(oacc[bn * 2], ph, vh0);
                mma16816(oacc[bn * 2], pl, vh0);
                mma16816(oacc[bn * 2 + 1], ph, vh1);
                mma16816(oacc[bn * 2 + 1], pl, vh1);
            }
        }
        int row = base + wm * 16 + (lane >> 2);
#pragma unroll
        for (int t = 0; t < 4; t++) {
            int col = h * 64 + wn * 32 + t * 8 + (lane & 3) * 2;
            float v00 = oacc[t][0], v01 = oacc[t][1];
            float v10 = oacc[t][2], v11 = oacc[t][3];
            __half h00 = __float2half_rn(v00), h01 = __float2half_rn(v01);
            __half h10 = __float2half_rn(v10), h11 = __float2half_rn(v11);
            *reinterpret_cast<__half2*>(&g_a_hi[(size_t)row * DM + col]) =
                __halves2half2(h00, h01);
            *reinterpret_cast<__half2*>(&g_a_hi[(size_t)(row + 8) * DM + col]) =
                __halves2half2(h10, h11);
            *reinterpret_cast<__half2*>(&g_a_lo[(size_t)row * DM + col]) =
                __halves2half2(__float2half_rn(v00 - __half2float(h00)),
                               __float2half_rn(v01 - __half2float(h01)));
            *reinterpret_cast<__half2*>(&g_a_lo[(size_t)(row + 8) * DM + col]) =
                __halves2half2(__float2half_rn(v10 - __half2float(h10)),
                               __float2half_rn(v11 - __half2float(h11)));
        }
    }
}

// ---------------- launch ----------------
extern "C" void kernel_launch(void* const* d_in, const int* in_sizes, int n_in,
                              void* d_out, int out_size) {
    const float* x  = (const float*)d_in[0];
    const float* Wq = (const float*)d_in[1];
    const float* bq = (const float*)d_in[2];
    const float* Wk = (const float*)d_in[3];
    const float* bk = (const float*)d_in[4];
    const float* Wv = (const float*)d_in[5];
    const float* bv = (const float*)d_in[6];
    const float* Wo = (const float*)d_in[7];
    const float* bo = (const float*)d_in[8];
    float* out = (float*)d_out;

    cudaFuncSetAttribute(gemm_qkv_mma, cudaFuncAttributeMaxDynamicSharedMemorySize, QKV_SMEM);
    cudaFuncSetAttribute(gemm_o_mma, cudaFuncAttributeMaxDynamicSharedMemorySize, O_SMEM);
    cudaFuncSetAttribute(attn_mma, cudaFuncAttributeMaxDynamicSharedMemorySize, ATTN_B);

    convert_split<<<dim3(XSZ / 1024, 5), 256>>>(x, Wq, Wk, Wv, Wo);

    gemm_qkv_mma<<<dim3(24, 32), 128, QKV_SMEM>>>(bq, bk, bv);

    attn_mma<<<dim3(32, 8), 256, ATTN_B>>>();

    gemm_o_mma<<<dim3(8, 64), 128, O_SMEM>>>(bo, out);
}

// round 13
// speedup vs baseline: 1.8066x; 1.2136x over previous
#include <cuda_runtime.h>
#include <cuda_fp16.h>
#include <stdint.h>

#define S_LEN 2048
#define DM 512
#define NH 8
#define WIN 64
#define SCALE 0.125f
#define WSZ (512*512)
#define XSZ (2048*512)

// ---------------- scratch (no allocation allowed) ----------------
__device__ __align__(16) __half g_x_hi[XSZ];                     // x: hi only
__device__ __align__(16) __half g_w_hi[4 * WSZ];                 // weights: hi only
__device__ __align__(16) __half g_q_hi[XSZ], g_q_lo[XSZ];        // q: exact split
__device__ __align__(16) __half g_k_hi[XSZ];                     // K: hi only
__device__ __align__(16) __half g_vt_hi[XSZ];                    // V^T: hi only [512][2048]
__device__ __align__(16) __half g_a_hi[XSZ];                     // attn out: hi only

// ---------------- PTX helpers (baseline sm_80+, compile for compute_103) -----
__device__ __forceinline__ uint32_t smem_u32(const void* p) {
    uint32_t a;
    asm("{ .reg .u64 t; cvta.to.shared.u64 t, %1; cvt.u32.u64 %0, t; }"
        : "=r"(a) : "l"(p));
    return a;
}
__device__ __forceinline__ void cp16(uint32_t s, const void* g) {
    asm volatile("cp.async.cg.shared.global [%0], [%1], 16;"
                 :: "r"(s), "l"(g) : "memory");
}
__device__ __forceinline__ void cp_commit() {
    asm volatile("cp.async.commit_group;" ::: "memory");
}
template<int N> __device__ __forceinline__ void cp_wait() {
    asm volatile("cp.async.wait_group %0;" :: "n"(N) : "memory");
}
__device__ __forceinline__ void ldsm_x4(uint32_t& r0, uint32_t& r1,
                                        uint32_t& r2, uint32_t& r3, uint32_t a) {
    asm volatile("ldmatrix.sync.aligned.m8n8.x4.shared.b16 {%0,%1,%2,%3}, [%4];"
                 : "=r"(r0), "=r"(r1), "=r"(r2), "=r"(r3) : "r"(a));
}
__device__ __forceinline__ void mma16816(float c[4], const uint32_t a[4],
                                         const uint32_t b[2]) {
    asm volatile(
        "mma.sync.aligned.m16n8k16.row.col.f32.f16.f16.f32 "
        "{%0,%1,%2,%3}, {%4,%5,%6,%7}, {%8,%9}, {%0,%1,%2,%3};"
        : "+f"(c[0]), "+f"(c[1]), "+f"(c[2]), "+f"(c[3])
        : "r"(a[0]), "r"(a[1]), "r"(a[2]), "r"(a[3]), "r"(b[0]), "r"(b[1]));
}

// ---------------- conversion: fp32 -> fp16 (hi only) --------------------------
__global__ __launch_bounds__(256)
void convert_split(const float* __restrict__ x,
                   const float* __restrict__ wq, const float* __restrict__ wk,
                   const float* __restrict__ wv, const float* __restrict__ wo)
{
    const int tn = blockIdx.y;
    const float* src = (tn == 0) ? x : (tn == 1) ? wq : (tn == 2) ? wk
                       : (tn == 3) ? wv : wo;
    const int n = (tn == 0) ? XSZ : WSZ;
    __half* hi = (tn == 0) ? g_x_hi : g_w_hi + (tn - 1) * WSZ;
    int i4 = (blockIdx.x * 256 + threadIdx.x) * 4;
    if (i4 >= n) return;
    float4 v = *reinterpret_cast<const float4*>(&src[i4]);
    reinterpret_cast<__half2*>(hi + i4)[0] =
        __halves2half2(__float2half_rn(v.x), __float2half_rn(v.y));
    reinterpret_cast<__half2*>(hi + i4)[1] =
        __halves2half2(__float2half_rn(v.z), __float2half_rn(v.w));
}

// ---------------- 1-term fp16 GEMM: BMx64 tile, K-chunk=64, 144B rows --------
// C = A·B^T (+ bias), both operands single fp16.
template<int BM>
__device__ __forceinline__ void gemm_body(
    const __half* __restrict__ A, const __half* __restrict__ Bhi,
    const float* __restrict__ bias, int mode,
    __half* __restrict__ oHi, __half* __restrict__ oLo,
    float* __restrict__ oF, int rowBase, int colBase)
{
    constexpr int MI   = BM / 32;
    constexpr int OBH  = BM * 144;
    constexpr int GBUF = (BM + 64) * 144;
    constexpr int NAOP = BM * 8;
    constexpr int ITER = (NAOP + 512) / 128;

    extern __shared__ __align__(16) char dynsm[];
    const uint32_t sb = smem_u32(dynsm);
    const int tid = threadIdx.x, lane = tid & 31, wid = tid >> 5;
    const int wm = wid >> 1, wn = wid & 1;         // warps: 2 (m) x 2 (n)
    const int a_row = (lane & 7) + ((lane >> 3) & 1) * 8, a_k = (lane >> 4) * 8;
    const int b_row = (lane & 7) + (lane >> 4) * 8,       b_k = ((lane >> 3) & 1) * 8;

    float acc[MI][4][4] = {};

    auto stage = [&](int buf, int c) {
#pragma unroll
        for (int i = 0; i < ITER; i++) {
            int idx = tid + i * 128;
            const __half* src; int off, rbase, rem;
            if (idx < NAOP) { src = A;   off = 0;   rbase = rowBase; rem = idx; }
            else            { src = Bhi; off = OBH; rbase = colBase; rem = idx - NAOP; }
            int row = rem >> 3, cc = rem & 7;
            cp16(sb + (uint32_t)(buf * GBUF + off + row * 144 + cc * 16),
                 src + ((size_t)(rbase + row) * DM + c * 64 + cc * 8));
        }
        cp_commit();
    };

    stage(0, 0);
    for (int c = 0; c < 8; c++) {
        cp_wait<0>();
        __syncthreads();
        if (c < 7) stage((c + 1) & 1, c + 1);
        const uint32_t bb = sb + (uint32_t)((c & 1) * GBUF);
#pragma unroll
        for (int k16 = 0; k16 < 4; k16++) {
            uint32_t ah[MI][4], bh[4][2];
#pragma unroll
            for (int mi = 0; mi < MI; mi++) {
                uint32_t o = (uint32_t)((wm * (BM / 2) + mi * 16 + a_row) * 144 +
                                        (k16 * 16 + a_k) * 2);
                ldsm_x4(ah[mi][0], ah[mi][1], ah[mi][2], ah[mi][3], bb + o);
            }
#pragma unroll
            for (int bn = 0; bn < 2; bn++) {
                uint32_t o = (uint32_t)((wn * 32 + bn * 16 + b_row) * 144 +
                                        (k16 * 16 + b_k) * 2);
                uint32_t r0, r1, r2, r3;
                ldsm_x4(r0, r1, r2, r3, bb + OBH + o);
                bh[bn * 2][0] = r0; bh[bn * 2][1] = r1;
                bh[bn * 2 + 1][0] = r2; bh[bn * 2 + 1][1] = r3;
            }
#pragma unroll
            for (int mi = 0; mi < MI; mi++)
#pragma unroll
                for (int ni = 0; ni < 4; ni++)
                    mma16816(acc[mi][ni], ah[mi], bh[ni]);
        }
    }

#pragma unroll
    for (int mi = 0; mi < MI; mi++) {
        int row = rowBase + wm * (BM / 2) + mi * 16 + (lane >> 2);
#pragma unroll
        for (int ni = 0; ni < 4; ni++) {
            int col = colBase + wn * 32 + ni * 8 + (lane & 3) * 2;
            float b0 = bias[col], b1 = bias[col + 1];
            float v00 = acc[mi][ni][0] + b0, v01 = acc[mi][ni][1] + b1;
            float v10 = acc[mi][ni][2] + b0, v11 = acc[mi][ni][3] + b1;
            if (mode == 2) {
                *reinterpret_cast<float2*>(&oF[(size_t)row * DM + col]) =
                    make_float2(v00, v01);
                *reinterpret_cast<float2*>(&oF[(size_t)(row + 8) * DM + col]) =
                    make_float2(v10, v11);
            } else if (mode == 0) {
                __half h00 = __float2half_rn(v00), h01 = __float2half_rn(v01);
                __half h10 = __float2half_rn(v10), h11 = __float2half_rn(v11);
                *reinterpret_cast<__half2*>(&oHi[(size_t)row * DM + col]) =
                    __halves2half2(h00, h01);
                *reinterpret_cast<__half2*>(&oHi[(size_t)(row + 8) * DM + col]) =
                    __halves2half2(h10, h11);
                if (oLo) {
                    *reinterpret_cast<__half2*>(&oLo[(size_t)row * DM + col]) =
                        __halves2half2(__float2half_rn(v00 - __half2float(h00)),
                                       __float2half_rn(v01 - __half2float(h01)));
                    *reinterpret_cast<__half2*>(&oLo[(size_t)(row + 8) * DM + col]) =
                        __halves2half2(__float2half_rn(v10 - __half2float(h10)),
                                       __float2half_rn(v11 - __half2float(h11)));
                }
            } else {
                oHi[(size_t)col * S_LEN + row] = __float2half_rn(v00);
                oHi[(size_t)(col + 1) * S_LEN + row] = __float2half_rn(v01);
                oHi[(size_t)col * S_LEN + row + 8] = __float2half_rn(v10);
                oHi[(size_t)(col + 1) * S_LEN + row + 8] = __float2half_rn(v11);
            }
        }
    }
}

#define QKV_SMEM ((64 + 64) * 144 * 2)   // 36864
#define O_SMEM   ((32 + 64) * 144 * 2)   // 27648

// QKV: grid (24, 32) = 768 CTAs.
__global__ __launch_bounds__(128, 4)
void gemm_qkv_mma(const float* __restrict__ bq, const float* __restrict__ bk,
                  const float* __restrict__ bv)
{
    const int which = blockIdx.x >> 3;
    const int colBase = (blockIdx.x & 7) * 64;
    const int rowBase = blockIdx.y * 64;
    const float* bias = (which == 0) ? bq : (which == 1) ? bk : bv;
    __half *oh, *ol; int mode;
    if (which == 0)      { oh = g_q_hi;  ol = g_q_lo; mode = 0; }
    else if (which == 1) { oh = g_k_hi;  ol = nullptr; mode = 0; }
    else                 { oh = g_vt_hi; ol = nullptr; mode = 1; }
    gemm_body<64>(g_x_hi, g_w_hi + which * WSZ,
                  bias, mode, oh, ol, nullptr, rowBase, colBase);
}

// O: grid (8, 64) = 512 CTAs, 32-row tiles.
__global__ __launch_bounds__(128, 4)
void gemm_o_mma(const float* __restrict__ bo, float* __restrict__ out)
{
    gemm_body<32>(g_a_hi, g_w_hi + 3 * WSZ,
                  bo, 2, nullptr, nullptr, out, blockIdx.y * 32, blockIdx.x * 64);
}

// ---------------- tensor-core banded attention (2-term Q/P, 1-term K/V) ------
#define AQH 0
#define AQL 9216
#define AKH 18432
#define AVH 46080
#define ASF 71680
#define APH AKH              /* P-hi overlays K after S is computed */
#define APL 122880
#define ATTN_B 148480

__global__ __launch_bounds__(256)
void attn_mma()
{
    extern __shared__ __align__(16) char dynsm[];
    const uint32_t sb = smem_u32(dynsm);
    const int tid = threadIdx.x, lane = tid & 31, wid = tid >> 5;
    const int h = blockIdx.y;
    const int base = blockIdx.x * 64;
    const int j0 = base - WIN;

#pragma unroll
    for (int i = 0; i < 4; i++) {                       // Q hi+lo [64][64]
        int idx = tid + i * 256;
        int arr = idx >> 9, rem = idx & 511;
        int row = rem >> 3, cc = rem & 7;
        cp16(sb + (arr ? AQL : AQH) + (uint32_t)(row * 144 + cc * 16),
             (arr ? g_q_lo : g_q_hi) + ((size_t)(base + row) * DM + h * 64 + cc * 8));
    }
#pragma unroll
    for (int i = 0; i < 6; i++) {                       // K hi [192][64]
        int idx = tid + i * 256;
        int row = idx >> 3, cc = idx & 7;
        int j = j0 + row;
        uint32_t off = AKH + (uint32_t)(row * 144 + cc * 16);
        if (j >= 0 && j < S_LEN)
            cp16(sb + off, g_k_hi + ((size_t)j * DM + h * 64 + cc * 8));
        else
            *reinterpret_cast<uint4*>(dynsm + off) = make_uint4(0, 0, 0, 0);
    }
#pragma unroll
    for (int i = 0; i < 6; i++) {                       // V^T hi [64][192]
        int idx = tid + i * 256;
        int row = idx / 24, cc = idx % 24;
        int j = j0 + cc * 8;
        uint32_t off = AVH + (uint32_t)(row * 400 + cc * 16);
        if (j >= 0 && j + 8 <= S_LEN)
            cp16(sb + off, g_vt_hi + ((size_t)(h * 64 + row) * S_LEN + j));
        else
            *reinterpret_cast<uint4*>(dynsm + off) = make_uint4(0, 0, 0, 0);
    }
    cp_commit();
    cp_wait<0>();
    __syncthreads();

    const int a_row = (lane & 7) + ((lane >> 3) & 1) * 8, a_k = (lane >> 4) * 8;
    const int b_row = (lane & 7) + (lane >> 4) * 8,       b_k = ((lane >> 3) & 1) * 8;
    const int wm = wid >> 1, wn = wid & 1;

    // ---- S = (Qh+Ql)·Kh^T ----
    {
        float sacc[12][4] = {};
#pragma unroll
        for (int k16 = 0; k16 < 4; k16++) {
            uint32_t ah[4], al[4];
            uint32_t oA = (uint32_t)((wm * 16 + a_row) * 144 + (k16 * 16 + a_k) * 2);
            ldsm_x4(ah[0], ah[1], ah[2], ah[3], sb + AQH + oA);
            ldsm_x4(al[0], al[1], al[2], al[3], sb + AQL + oA);
#pragma unroll
            for (int t = 0; t < 6; t++) {
                uint32_t oB = (uint32_t)((wn * 96 + t * 16 + b_row) * 144 +
                                         (k16 * 16 + b_k) * 2);
                uint32_t r0, r1, r2, r3, b0[2], b1[2];
                ldsm_x4(r0, r1, r2, r3, sb + AKH + oB);
                b0[0] = r0; b0[1] = r1; b1[0] = r2; b1[1] = r3;
                mma16816(sacc[t * 2], ah, b0);
                mma16816(sacc[t * 2], al, b0);
                mma16816(sacc[t * 2 + 1], ah, b1);
                mma16816(sacc[t * 2 + 1], al, b1);
            }
        }
        float* S = reinterpret_cast<float*>(dynsm + ASF);
        int row = wm * 16 + (lane >> 2);
#pragma unroll
        for (int t = 0; t < 12; t++) {
            int col = wn * 96 + t * 8 + (lane & 3) * 2;
            *reinterpret_cast<float2*>(&S[row * 200 + col]) =
                make_float2(sacc[t][0], sacc[t][1]);
            *reinterpret_cast<float2*>(&S[(row + 8) * 200 + col]) =
                make_float2(sacc[t][2], sacc[t][3]);
        }
    }
    __syncthreads();

    // ---- masked softmax; write normalized P (fp16 hi/lo) ----
    {
        float* S = reinterpret_cast<float*>(dynsm + ASF);
#pragma unroll
        for (int r8 = 0; r8 < 8; r8++) {
            int m = wid * 8 + r8;
            int nlo = m, nhi = m + 128;
            if (-j0 > nlo) nlo = -j0;
            if (2047 - j0 < nhi) nhi = 2047 - j0;
            float v[6], mx = -1e30f;
#pragma unroll
            for (int i = 0; i < 6; i++) {
                int n = lane + 32 * i;
                float sv = S[m * 200 + n] * SCALE;
                v[i] = (n >= nlo && n <= nhi) ? sv : -1e30f;
                mx = fmaxf(mx, v[i]);
            }
#pragma unroll
            for (int o = 16; o; o >>= 1)
                mx = fmaxf(mx, __shfl_xor_sync(0xffffffffu, mx, o));
            float e[6], sum = 0.f;
#pragma unroll
            for (int i = 0; i < 6; i++) { e[i] = __expf(v[i] - mx); sum += e[i]; }
#pragma unroll
            for (int o = 16; o; o >>= 1)
                sum += __shfl_xor_sync(0xffffffffu, sum, o);
            float inv = 1.f / sum;
#pragma unroll
            for (int i = 0; i < 6; i++) {
                int n = lane + 32 * i;
                float p = e[i] * inv;
                __half ph = __float2half_rn(p);
                __half pl = __float2half_rn(p - __half2float(ph));
                *reinterpret_cast<__half*>(dynsm + APH + m * 400 + n * 2) = ph;
                *reinterpret_cast<__half*>(dynsm + APL + m * 400 + n * 2) = pl;
            }
        }
    }
    __syncthreads();

    // ---- O = (Ph+Pl)·Vh ----
    {
        float oacc[4][4] = {};
#pragma unroll
        for (int k16 = 0; k16 < 12; k16++) {
            uint32_t ph[4], pl[4];
            uint32_t oA = (uint32_t)((wm * 16 + a_row) * 400 + (k16 * 16 + a_k) * 2);
            ldsm_x4(ph[0], ph[1], ph[2], ph[3], sb + APH + oA);
            ldsm_x4(pl[0], pl[1], pl[2], pl[3], sb + APL + oA);
#pragma unroll
            for (int bn = 0; bn < 2; bn++) {
                uint32_t oB = (uint32_t)((wn * 32 + bn * 16 + b_row) * 400 +
                                         (k16 * 16 + b_k) * 2);
                uint32_t r0, r1, r2, r3, vh0[2], vh1[2];
                ldsm_x4(r0, r1, r2, r3, sb + AVH + oB);
                vh0[0] = r0; vh0[1] = r1; vh1[0] = r2; vh1[1] = r3;
                mma16816(oacc[bn * 2], ph, vh0);
                mma16816(oacc[bn * 2], pl, vh0);
                mma16816(oacc[bn * 2 + 1], ph, vh1);
                mma16816(oacc[bn * 2 + 1], pl, vh1);
            }
        }
        int row = base + wm * 16 + (lane >> 2);
#pragma unroll
        for (int t = 0; t < 4; t++) {
            int col = h * 64 + wn * 32 + t * 8 + (lane & 3) * 2;
            *reinterpret_cast<__half2*>(&g_a_hi[(size_t)row * DM + col]) =
                __halves2half2(__float2half_rn(oacc[t][0]), __float2half_rn(oacc[t][1]));
            *reinterpret_cast<__half2*>(&g_a_hi[(size_t)(row + 8) * DM + col]) =
                __halves2half2(__float2half_rn(oacc[t][2]), __float2half_rn(oacc[t][3]));
        }
    }
}

// ---------------- launch ----------------
extern "C" void kernel_launch(void* const* d_in, const int* in_sizes, int n_in,
                              void* d_out, int out_size) {
    const float* x  = (const float*)d_in[0];
    const float* Wq = (const float*)d_in[1];
    const float* bq = (const float*)d_in[2];
    const float* Wk = (const float*)d_in[3];
    const float* bk = (const float*)d_in[4];
    const float* Wv = (const float*)d_in[5];
    const float* bv = (const float*)d_in[6];
    const float* Wo = (const float*)d_in[7];
    const float* bo = (const float*)d_in[8];
    float* out = (float*)d_out;

    cudaFuncSetAttribute(gemm_qkv_mma, cudaFuncAttributeMaxDynamicSharedMemorySize, QKV_SMEM);
    cudaFuncSetAttribute(gemm_o_mma, cudaFuncAttributeMaxDynamicSharedMemorySize, O_SMEM);
    cudaFuncSetAttribute(attn_mma, cudaFuncAttributeMaxDynamicSharedMemorySize, ATTN_B);

    convert_split<<<dim3(XSZ / 1024, 5), 256>>>(x, Wq, Wk, Wv, Wo);

    gemm_qkv_mma<<<dim3(24, 32), 128, QKV_SMEM>>>(bq, bk, bv);

    attn_mma<<<dim3(32, 8), 256, ATTN_B>>>();

    gemm_o_mma<<<dim3(8, 64), 128, O_SMEM>>>(bo, out);
}

// round 14
// speedup vs baseline: 2.0804x; 1.1516x over previous
#include <cuda_runtime.h>
#include <cuda_fp16.h>
#include <stdint.h>

#define S_LEN 2048
#define DM 512
#define NH 8
#define WIN 64
#define SCALE 0.125f
#define WSZ (512*512)
#define XSZ (2048*512)

// ---------------- scratch (no allocation allowed) ----------------
__device__ __align__(16) __half g_x_hi[XSZ];                     // x: hi only
__device__ __align__(16) __half g_w_hi[4 * WSZ];                 // weights: hi only
__device__ __align__(16) __half g_q_hi[XSZ];                     // q: hi only
__device__ __align__(16) __half g_k_hi[XSZ];                     // K: hi only
__device__ __align__(16) __half g_vt_hi[XSZ];                    // V^T: hi only [512][2048]
__device__ __align__(16) __half g_a_hi[XSZ];                     // attn out: hi only

// ---------------- PTX helpers (baseline sm_80+, compile for compute_103) -----
__device__ __forceinline__ uint32_t smem_u32(const void* p) {
    uint32_t a;
    asm("{ .reg .u64 t; cvta.to.shared.u64 t, %1; cvt.u32.u64 %0, t; }"
        : "=r"(a) : "l"(p));
    return a;
}
__device__ __forceinline__ void cp16(uint32_t s, const void* g) {
    asm volatile("cp.async.cg.shared.global [%0], [%1], 16;"
                 :: "r"(s), "l"(g) : "memory");
}
__device__ __forceinline__ void cp_commit() {
    asm volatile("cp.async.commit_group;" ::: "memory");
}
template<int N> __device__ __forceinline__ void cp_wait() {
    asm volatile("cp.async.wait_group %0;" :: "n"(N) : "memory");
}
__device__ __forceinline__ void ldsm_x4(uint32_t& r0, uint32_t& r1,
                                        uint32_t& r2, uint32_t& r3, uint32_t a) {
    asm volatile("ldmatrix.sync.aligned.m8n8.x4.shared.b16 {%0,%1,%2,%3}, [%4];"
                 : "=r"(r0), "=r"(r1), "=r"(r2), "=r"(r3) : "r"(a));
}
__device__ __forceinline__ void mma16816(float c[4], const uint32_t a[4],
                                         const uint32_t b[2]) {
    asm volatile(
        "mma.sync.aligned.m16n8k16.row.col.f32.f16.f16.f32 "
        "{%0,%1,%2,%3}, {%4,%5,%6,%7}, {%8,%9}, {%0,%1,%2,%3};"
        : "+f"(c[0]), "+f"(c[1]), "+f"(c[2]), "+f"(c[3])
        : "r"(a[0]), "r"(a[1]), "r"(a[2]), "r"(a[3]), "r"(b[0]), "r"(b[1]));
}

// ---------------- conversion: fp32 -> fp16 (hi only) --------------------------
__global__ __launch_bounds__(256)
void convert_split(const float* __restrict__ x,
                   const float* __restrict__ wq, const float* __restrict__ wk,
                   const float* __restrict__ wv, const float* __restrict__ wo)
{
    const int tn = blockIdx.y;
    const float* src = (tn == 0) ? x : (tn == 1) ? wq : (tn == 2) ? wk
                       : (tn == 3) ? wv : wo;
    const int n = (tn == 0) ? XSZ : WSZ;
    __half* hi = (tn == 0) ? g_x_hi : g_w_hi + (tn - 1) * WSZ;
    int i4 = (blockIdx.x * 256 + threadIdx.x) * 4;
    if (i4 >= n) return;
    float4 v = *reinterpret_cast<const float4*>(&src[i4]);
    reinterpret_cast<__half2*>(hi + i4)[0] =
        __halves2half2(__float2half_rn(v.x), __float2half_rn(v.y));
    reinterpret_cast<__half2*>(hi + i4)[1] =
        __halves2half2(__float2half_rn(v.z), __float2half_rn(v.w));
}

// ---------------- 1-term fp16 GEMM: BMx64 tile, K-chunk=64, 144B rows --------
template<int BM>
__device__ __forceinline__ void gemm_body(
    const __half* __restrict__ A, const __half* __restrict__ Bhi,
    const float* __restrict__ bias, int mode,
    __half* __restrict__ oHi,
    float* __restrict__ oF, int rowBase, int colBase)
{
    constexpr int MI   = BM / 32;
    constexpr int OBH  = BM * 144;
    constexpr int GBUF = (BM + 64) * 144;
    constexpr int NAOP = BM * 8;
    constexpr int ITER = (NAOP + 512) / 128;

    extern __shared__ __align__(16) char dynsm[];
    const uint32_t sb = smem_u32(dynsm);
    const int tid = threadIdx.x, lane = tid & 31, wid = tid >> 5;
    const int wm = wid >> 1, wn = wid & 1;
    const int a_row = (lane & 7) + ((lane >> 3) & 1) * 8, a_k = (lane >> 4) * 8;
    const int b_row = (lane & 7) + (lane >> 4) * 8,       b_k = ((lane >> 3) & 1) * 8;

    float acc[MI][4][4] = {};

    auto stage = [&](int buf, int c) {
#pragma unroll
        for (int i = 0; i < ITER; i++) {
            int idx = tid + i * 128;
            const __half* src; int off, rbase, rem;
            if (idx < NAOP) { src = A;   off = 0;   rbase = rowBase; rem = idx; }
            else            { src = Bhi; off = OBH; rbase = colBase; rem = idx - NAOP; }
            int row = rem >> 3, cc = rem & 7;
            cp16(sb + (uint32_t)(buf * GBUF + off + row * 144 + cc * 16),
                 src + ((size_t)(rbase + row) * DM + c * 64 + cc * 8));
        }
        cp_commit();
    };

    stage(0, 0);
    for (int c = 0; c < 8; c++) {
        cp_wait<0>();
        __syncthreads();
        if (c < 7) stage((c + 1) & 1, c + 1);
        const uint32_t bb = sb + (uint32_t)((c & 1) * GBUF);
#pragma unroll
        for (int k16 = 0; k16 < 4; k16++) {
            uint32_t ah[MI][4], bh[4][2];
#pragma unroll
            for (int mi = 0; mi < MI; mi++) {
                uint32_t o = (uint32_t)((wm * (BM / 2) + mi * 16 + a_row) * 144 +
                                        (k16 * 16 + a_k) * 2);
                ldsm_x4(ah[mi][0], ah[mi][1], ah[mi][2], ah[mi][3], bb + o);
            }
#pragma unroll
            for (int bn = 0; bn < 2; bn++) {
                uint32_t o = (uint32_t)((wn * 32 + bn * 16 + b_row) * 144 +
                                        (k16 * 16 + b_k) * 2);
                uint32_t r0, r1, r2, r3;
                ldsm_x4(r0, r1, r2, r3, bb + OBH + o);
                bh[bn * 2][0] = r0; bh[bn * 2][1] = r1;
                bh[bn * 2 + 1][0] = r2; bh[bn * 2 + 1][1] = r3;
            }
#pragma unroll
            for (int mi = 0; mi < MI; mi++)
#pragma unroll
                for (int ni = 0; ni < 4; ni++)
                    mma16816(acc[mi][ni], ah[mi], bh[ni]);
        }
    }

#pragma unroll
    for (int mi = 0; mi < MI; mi++) {
        int row = rowBase + wm * (BM / 2) + mi * 16 + (lane >> 2);
#pragma unroll
        for (int ni = 0; ni < 4; ni++) {
            int col = colBase + wn * 32 + ni * 8 + (lane & 3) * 2;
            float b0 = bias[col], b1 = bias[col + 1];
            float v00 = acc[mi][ni][0] + b0, v01 = acc[mi][ni][1] + b1;
            float v10 = acc[mi][ni][2] + b0, v11 = acc[mi][ni][3] + b1;
            if (mode == 2) {
                *reinterpret_cast<float2*>(&oF[(size_t)row * DM + col]) =
                    make_float2(v00, v01);
                *reinterpret_cast<float2*>(&oF[(size_t)(row + 8) * DM + col]) =
                    make_float2(v10, v11);
            } else if (mode == 0) {
                *reinterpret_cast<__half2*>(&oHi[(size_t)row * DM + col]) =
                    __halves2half2(__float2half_rn(v00), __float2half_rn(v01));
                *reinterpret_cast<__half2*>(&oHi[(size_t)(row + 8) * DM + col]) =
                    __halves2half2(__float2half_rn(v10), __float2half_rn(v11));
            } else {
                oHi[(size_t)col * S_LEN + row] = __float2half_rn(v00);
                oHi[(size_t)(col + 1) * S_LEN + row] = __float2half_rn(v01);
                oHi[(size_t)col * S_LEN + row + 8] = __float2half_rn(v10);
                oHi[(size_t)(col + 1) * S_LEN + row + 8] = __float2half_rn(v11);
            }
        }
    }
}

#define QKV_SMEM ((64 + 64) * 144 * 2)   // 36864
#define O_SMEM   ((32 + 64) * 144 * 2)   // 27648

// QKV: grid (24, 32) = 768 CTAs.
__global__ __launch_bounds__(128, 4)
void gemm_qkv_mma(const float* __restrict__ bq, const float* __restrict__ bk,
                  const float* __restrict__ bv)
{
    const int which = blockIdx.x >> 3;
    const int colBase = (blockIdx.x & 7) * 64;
    const int rowBase = blockIdx.y * 64;
    const float* bias = (which == 0) ? bq : (which == 1) ? bk : bv;
    __half* oh; int mode;
    if (which == 0)      { oh = g_q_hi;  mode = 0; }
    else if (which == 1) { oh = g_k_hi;  mode = 0; }
    else                 { oh = g_vt_hi; mode = 1; }
    gemm_body<64>(g_x_hi, g_w_hi + which * WSZ,
                  bias, mode, oh, nullptr, rowBase, colBase);
}

// O: grid (8, 64) = 512 CTAs, 32-row tiles.
__global__ __launch_bounds__(128, 4)
void gemm_o_mma(const float* __restrict__ bo, float* __restrict__ out)
{
    gemm_body<32>(g_a_hi, g_w_hi + 3 * WSZ,
                  bo, 2, nullptr, out, blockIdx.y * 32, blockIdx.x * 64);
}

// ---------------- tensor-core banded attention (1-term everywhere) -----------
// S = Qh·Kh^T ; masked softmax ; O = Ph·Vh.   smem ~111KB -> 2 CTAs/SM.
#define AQH 0
#define AKH 9216
#define AVH 36864
#define ASF 62464
#define APH AKH              /* P (64x400B=25600) overlays K (27648) */
#define ATTN_B 113664

__global__ __launch_bounds__(256)
void attn_mma()
{
    extern __shared__ __align__(16) char dynsm[];
    const uint32_t sb = smem_u32(dynsm);
    const int tid = threadIdx.x, lane = tid & 31, wid = tid >> 5;
    const int h = blockIdx.y;
    const int base = blockIdx.x * 64;
    const int j0 = base - WIN;

#pragma unroll
    for (int i = 0; i < 2; i++) {                       // Q hi [64][64]
        int idx = tid + i * 256;
        int row = idx >> 3, cc = idx & 7;
        cp16(sb + AQH + (uint32_t)(row * 144 + cc * 16),
             g_q_hi + ((size_t)(base + row) * DM + h * 64 + cc * 8));
    }
#pragma unroll
    for (int i = 0; i < 6; i++) {                       // K hi [192][64]
        int idx = tid + i * 256;
        int row = idx >> 3, cc = idx & 7;
        int j = j0 + row;
        uint32_t off = AKH + (uint32_t)(row * 144 + cc * 16);
        if (j >= 0 && j < S_LEN)
            cp16(sb + off, g_k_hi + ((size_t)j * DM + h * 64 + cc * 8));
        else
            *reinterpret_cast<uint4*>(dynsm + off) = make_uint4(0, 0, 0, 0);
    }
#pragma unroll
    for (int i = 0; i < 6; i++) {                       // V^T hi [64][192]
        int idx = tid + i * 256;
        int row = idx / 24, cc = idx % 24;
        int j = j0 + cc * 8;
        uint32_t off = AVH + (uint32_t)(row * 400 + cc * 16);
        if (j >= 0 && j + 8 <= S_LEN)
            cp16(sb + off, g_vt_hi + ((size_t)(h * 64 + row) * S_LEN + j));
        else
            *reinterpret_cast<uint4*>(dynsm + off) = make_uint4(0, 0, 0, 0);
    }
    cp_commit();
    cp_wait<0>();
    __syncthreads();

    const int a_row = (lane & 7) + ((lane >> 3) & 1) * 8, a_k = (lane >> 4) * 8;
    const int b_row = (lane & 7) + (lane >> 4) * 8,       b_k = ((lane >> 3) & 1) * 8;
    const int wm = wid >> 1, wn = wid & 1;

    // ---- S = Qh·Kh^T ----
    {
        float sacc[12][4] = {};
#pragma unroll
        for (int k16 = 0; k16 < 4; k16++) {
            uint32_t ah[4];
            uint32_t oA = (uint32_t)((wm * 16 + a_row) * 144 + (k16 * 16 + a_k) * 2);
            ldsm_x4(ah[0], ah[1], ah[2], ah[3], sb + AQH + oA);
#pragma unroll
            for (int t = 0; t < 6; t++) {
                uint32_t oB = (uint32_t)((wn * 96 + t * 16 + b_row) * 144 +
                                         (k16 * 16 + b_k) * 2);
                uint32_t r0, r1, r2, r3, b0[2], b1[2];
                ldsm_x4(r0, r1, r2, r3, sb + AKH + oB);
                b0[0] = r0; b0[1] = r1; b1[0] = r2; b1[1] = r3;
                mma16816(sacc[t * 2], ah, b0);
                mma16816(sacc[t * 2 + 1], ah, b1);
            }
        }
        float* S = reinterpret_cast<float*>(dynsm + ASF);
        int row = wm * 16 + (lane >> 2);
#pragma unroll
        for (int t = 0; t < 12; t++) {
            int col = wn * 96 + t * 8 + (lane & 3) * 2;
            *reinterpret_cast<float2*>(&S[row * 200 + col]) =
                make_float2(sacc[t][0], sacc[t][1]);
            *reinterpret_cast<float2*>(&S[(row + 8) * 200 + col]) =
                make_float2(sacc[t][2], sacc[t][3]);
        }
    }
    __syncthreads();

    // ---- masked softmax; write normalized P (fp16) over K ----
    {
        float* S = reinterpret_cast<float*>(dynsm + ASF);
#pragma unroll
        for (int r8 = 0; r8 < 8; r8++) {
            int m = wid * 8 + r8;
            int nlo = m, nhi = m + 128;
            if (-j0 > nlo) nlo = -j0;
            if (2047 - j0 < nhi) nhi = 2047 - j0;
            float v[6], mx = -1e30f;
#pragma unroll
            for (int i = 0; i < 6; i++) {
                int n = lane + 32 * i;
                float sv = S[m * 200 + n] * SCALE;
                v[i] = (n >= nlo && n <= nhi) ? sv : -1e30f;
                mx = fmaxf(mx, v[i]);
            }
#pragma unroll
            for (int o = 16; o; o >>= 1)
                mx = fmaxf(mx, __shfl_xor_sync(0xffffffffu, mx, o));
            float e[6], sum = 0.f;
#pragma unroll
            for (int i = 0; i < 6; i++) { e[i] = __expf(v[i] - mx); sum += e[i]; }
#pragma unroll
            for (int o = 16; o; o >>= 1)
                sum += __shfl_xor_sync(0xffffffffu, sum, o);
            float inv = 1.f / sum;
#pragma unroll
            for (int i = 0; i < 6; i++) {
                int n = lane + 32 * i;
                *reinterpret_cast<__half*>(dynsm + APH + m * 400 + n * 2) =
                    __float2half_rn(e[i] * inv);
            }
        }
    }
    __syncthreads();

    // ---- O = Ph·Vh ----
    {
        float oacc[4][4] = {};
#pragma unroll
        for (int k16 = 0; k16 < 12; k16++) {
            uint32_t ph[4];
            uint32_t oA = (uint32_t)((wm * 16 + a_row) * 400 + (k16 * 16 + a_k) * 2);
            ldsm_x4(ph[0], ph[1], ph[2], ph[3], sb + APH + oA);
#pragma unroll
            for (int bn = 0; bn < 2; bn++) {
                uint32_t oB = (uint32_t)((wn * 32 + bn * 16 + b_row) * 400 +
                                         (k16 * 16 + b_k) * 2);
                uint32_t r0, r1, r2, r3, vh0[2], vh1[2];
                ldsm_x4(r0, r1, r2, r3, sb + AVH + oB);
                vh0[0] = r0; vh0[1] = r1; vh1[0] = r2; vh1[1] = r3;
                mma16816(oacc[bn * 2], ph, vh0);
                mma16816(oacc[bn * 2 + 1], ph, vh1);
            }
        }
        int row = base + wm * 16 + (lane >> 2);
#pragma unroll
        for (int t = 0; t < 4; t++) {
            int col = h * 64 + wn * 32 + t * 8 + (lane & 3) * 2;
            *reinterpret_cast<__half2*>(&g_a_hi[(size_t)row * DM + col]) =
                __halves2half2(__float2half_rn(oacc[t][0]), __float2half_rn(oacc[t][1]));
            *reinterpret_cast<__half2*>(&g_a_hi[(size_t)(row + 8) * DM + col]) =
                __halves2half2(__float2half_rn(oacc[t][2]), __float2half_rn(oacc[t][3]));
        }
    }
}

// ---------------- launch ----------------
extern "C" void kernel_launch(void* const* d_in, const int* in_sizes, int n_in,
                              void* d_out, int out_size) {
    const float* x  = (const float*)d_in[0];
    const float* Wq = (const float*)d_in[1];
    const float* bq = (const float*)d_in[2];
    const float* Wk = (const float*)d_in[3];
    const float* bk = (const float*)d_in[4];
    const float* Wv = (const float*)d_in[5];
    const float* bv = (const float*)d_in[6];
    const float* Wo = (const float*)d_in[7];
    const float* bo = (const float*)d_in[8];
    float* out = (float*)d_out;

    cudaFuncSetAttribute(gemm_qkv_mma, cudaFuncAttributeMaxDynamicSharedMemorySize, QKV_SMEM);
    cudaFuncSetAttribute(gemm_o_mma, cudaFuncAttributeMaxDynamicSharedMemorySize, O_SMEM);
    cudaFuncSetAttribute(attn_mma, cudaFuncAttributeMaxDynamicSharedMemorySize, ATTN_B);

    convert_split<<<dim3(XSZ / 1024, 5), 256>>>(x, Wq, Wk, Wv, Wo);

    gemm_qkv_mma<<<dim3(24, 32), 128, QKV_SMEM>>>(bq, bk, bv);

    attn_mma<<<dim3(32, 8), 256, ATTN_B>>>();

    gemm_o_mma<<<dim3(8, 64), 128, O_SMEM>>>(bo, out);
}